// round 1
// baseline (speedup 1.0000x reference)
#include <cuda_runtime.h>
#include <cuda_bf16.h>
#include <math.h>

// ---------------- problem constants ----------------
#define SEQ     2048
#define DMODEL  1024
#define HKN     8
#define DK      64
#define HV      16
#define DV      64
#define KEYD    512            // HK*DK
#define VALD    1024           // HV*DV
#define CONVD   2048           // 2*KEYD + VALD
#define KW      4
#define NE      8
#define TOPK    2
#define IMOE    512

// output layout in d_out (floats): x | state | conv_state
#define OUT_X_OFF     0
#define OUT_STATE_OFF (SEQ*DMODEL)                 // 2097152
#define OUT_CONV_OFF  (OUT_STATE_OFF + HV*DK*DV)   // 2162688

// ---------------- scratch (device globals; no allocs allowed) ----------------
__device__ float g_h    [SEQ*DMODEL];
__device__ float g_qkvp [SEQ*CONVD];
__device__ float g_qkv  [SEQ*CONVD];
__device__ float g_z    [SEQ*VALD];
__device__ float g_a    [SEQ*HV];
__device__ float g_b    [SEQ*HV];
__device__ float g_qn   [SEQ*VALD];
__device__ float g_kn   [SEQ*VALD];
__device__ float g_beta [SEQ*HV];
__device__ float g_decay[SEQ*HV];
__device__ float g_o    [SEQ*VALD];
__device__ float g_attn [SEQ*DMODEL];
__device__ float g_x2   [SEQ*DMODEL];
__device__ float g_t    [SEQ*DMODEL];
__device__ int   g_topi [SEQ*TOPK];
__device__ float g_topw [SEQ*TOPK];
__device__ int   g_cnt  [NE];
__device__ int   g_list [NE*SEQ];
__device__ float g_lw   [NE*SEQ];
__device__ float g_gu   [(long)NE*SEQ*1024];
__device__ float g_act  [(long)NE*SEQ*IMOE];
__device__ float g_routed[SEQ*DMODEL];
__device__ float g_sg   [SEQ*VALD];
__device__ float g_su   [SEQ*VALD];
__device__ float g_sh   [SEQ*DMODEL];
__device__ float g_gate [SEQ];

// ---------------- helpers ----------------
__device__ __forceinline__ float warp_reduce(float v) {
    #pragma unroll
    for (int o = 16; o > 0; o >>= 1) v += __shfl_xor_sync(0xffffffffu, v, o);
    return v;
}
__device__ __forceinline__ float siluf(float x) { return x / (1.f + expf(-x)); }
__device__ __forceinline__ float sigmoidf(float x) { return 1.f / (1.f + expf(-x)); }

// ---------------- rms norm (row = 1024) ----------------
__global__ void rmsnorm_kernel(const float* __restrict__ x, const float* __restrict__ w,
                               float* __restrict__ y) {
    int row = blockIdx.x;
    int tid = threadIdx.x;
    const float* xr = x + (long)row * DMODEL;
    float v[4]; float ss = 0.f;
    #pragma unroll
    for (int i = 0; i < 4; i++) { v[i] = xr[tid + 256*i]; ss += v[i]*v[i]; }
    ss = warp_reduce(ss);
    __shared__ float sm[8];
    __shared__ float rtot;
    if ((tid & 31) == 0) sm[tid >> 5] = ss;
    __syncthreads();
    if (tid == 0) {
        float t2 = 0.f;
        #pragma unroll
        for (int i = 0; i < 8; i++) t2 += sm[i];
        rtot = rsqrtf(t2 / (float)DMODEL + 1e-6f);
    }
    __syncthreads();
    float r = rtot;
    float* yr = y + (long)row * DMODEL;
    #pragma unroll
    for (int i = 0; i < 4; i++)
        yr[tid + 256*i] = v[i] * r * (1.f + w[tid + 256*i]);
}

// ---------------- generic tiled GEMM 64x64x16, 256 thr, 4x4/thr ----------------
// C[M,N] = A[M,K] * B  ; BT: B is (N,K) row-major, else (K,N) row-major.
// AGATHER: A rows taken via gIdx list (Meff = gCnt[e]).
// CSCATTER: store atomically into C[tok, n] scaled by gW (Meff = gCnt[e]).
template<bool BT, bool AGATHER, bool CSCATTER>
__global__ void gemm_kernel(const float* __restrict__ Abase,
                            const float* __restrict__ Bbase,
                            float* __restrict__ Cbase,
                            int M, int N, int K,
                            long aStride, long bStride, long cStride,
                            const int* __restrict__ gIdx,
                            const int* __restrict__ gCnt,
                            const float* __restrict__ gW,
                            int gCap) {
    const int e = blockIdx.z;
    const float* A = Abase + (long)e * aStride;
    const float* B = Bbase + (long)e * bStride;
    float* C = Cbase + (long)e * cStride;

    int Meff = M;
    const int* lst = nullptr;
    const float* wl = nullptr;
    if (AGATHER || CSCATTER) {
        Meff = gCnt[e];
        lst = gIdx + e * gCap;
        wl  = gW  + e * gCap;
    }
    int m0 = blockIdx.y * 64;
    int n0 = blockIdx.x * 64;
    if (m0 >= Meff) return;

    __shared__ float As[16][64];
    __shared__ float Bs[16][64];
    int tid = threadIdx.x;
    int tx = tid & 15, ty = tid >> 4;
    float acc[4][4] = {};

    int aRow = tid >> 2;              // 0..63
    int aK   = (tid & 3) * 4;         // 0,4,8,12
    int aRowIdx = m0 + aRow;
    bool aInRange = aRowIdx < Meff;
    long aGlobRow = 0;
    if (aInRange) aGlobRow = AGATHER ? (long)lst[aRowIdx] : (long)aRowIdx;
    const float* aPtr = A + aGlobRow * K + aK;

    for (int k0 = 0; k0 < K; k0 += 16) {
        #pragma unroll
        for (int j = 0; j < 4; j++) {
            float v = 0.f;
            if (aInRange) v = aPtr[k0 + j];
            As[aK + j][aRow] = v;
        }
        if (BT) {
            int bN = tid >> 2; int bK = (tid & 3) * 4;
            bool ok = (n0 + bN) < N;
            const float* bp = B + (long)(n0 + bN) * K + k0 + bK;
            #pragma unroll
            for (int j = 0; j < 4; j++) {
                Bs[bK + j][bN] = ok ? bp[j] : 0.f;
            }
        } else {
            int bK = tid >> 4; int bN = (tid & 15) * 4;
            const float* bp = B + (long)(k0 + bK) * N + n0 + bN;
            #pragma unroll
            for (int j = 0; j < 4; j++) {
                Bs[bK][bN + j] = ((n0 + bN + j) < N) ? bp[j] : 0.f;
            }
        }
        __syncthreads();
        #pragma unroll
        for (int k = 0; k < 16; k++) {
            float a[4], b[4];
            #pragma unroll
            for (int i = 0; i < 4; i++) a[i] = As[k][ty*4 + i];
            #pragma unroll
            for (int j = 0; j < 4; j++) b[j] = Bs[k][tx*4 + j];
            #pragma unroll
            for (int i = 0; i < 4; i++)
                #pragma unroll
                for (int j = 0; j < 4; j++)
                    acc[i][j] += a[i] * b[j];
        }
        __syncthreads();
    }

    #pragma unroll
    for (int i = 0; i < 4; i++) {
        int m = m0 + ty*4 + i;
        if (m >= Meff) continue;
        if (CSCATTER) {
            int tok = lst[m];
            float w = wl[m];
            #pragma unroll
            for (int j = 0; j < 4; j++) {
                int n = n0 + tx*4 + j;
                if (n < N) atomicAdd(&C[(long)tok * N + n], w * acc[i][j]);
            }
        } else {
            #pragma unroll
            for (int j = 0; j < 4; j++) {
                int n = n0 + tx*4 + j;
                if (n < N) C[(long)m * N + n] = acc[i][j];
            }
        }
    }
}

// ---------------- depthwise causal conv (KW=4) + silu ----------------
__global__ void conv_silu_kernel(const float* __restrict__ qkvp,
                                 const float* __restrict__ conv_state,
                                 const float* __restrict__ w,
                                 float* __restrict__ out) {
    long idx = (long)blockIdx.x * blockDim.x + threadIdx.x;
    if (idx >= (long)SEQ * CONVD) return;
    int s = (int)(idx / CONVD);
    int c = (int)(idx % CONVD);
    float acc = 0.f;
    #pragma unroll
    for (int j = 0; j < KW; j++) {
        int p = s + j;
        float xv = (p < KW-1) ? conv_state[(long)p * CONVD + c]
                              : qkvp[(long)(p - (KW-1)) * CONVD + c];
        acc += xv * w[c * KW + j];
    }
    out[idx] = siluf(acc);
}

// ---------------- l2norm of q,k heads + repeat to HV + q scale ----------------
__global__ void l2norm_kernel(const float* __restrict__ qkv,
                              float* __restrict__ qn, float* __restrict__ kn) {
    int gw = blockIdx.x * 8 + (threadIdx.x >> 5);
    int lane = threadIdx.x & 31;
    int s = gw >> 4;
    int rr = gw & 15;
    bool isq = rr < 8;
    int hk = isq ? rr : rr - 8;
    long base = (long)s * CONVD + (isq ? 0 : KEYD) + hk * 64;
    float v0 = qkv[base + lane];
    float v1 = qkv[base + 32 + lane];
    float ss = warp_reduce(v0*v0 + v1*v1);
    float r = rsqrtf(ss + 1e-6f);
    float sc = isq ? 0.125f : 1.f;    // DK^-0.5 = 1/8 for q
    float o0 = v0 * r * sc, o1 = v1 * r * sc;
    float* dst = isq ? qn : kn;
    long b0 = (long)s * VALD + (2*hk) * 64;
    long b1 = (long)s * VALD + (2*hk + 1) * 64;
    dst[b0 + lane] = o0;       dst[b0 + 32 + lane] = o1;
    dst[b1 + lane] = o0;       dst[b1 + 32 + lane] = o1;
}

// ---------------- beta / decay ----------------
__global__ void decay_beta_kernel(const float* __restrict__ a, const float* __restrict__ b,
                                  const float* __restrict__ dtb, const float* __restrict__ alog,
                                  float* __restrict__ beta, float* __restrict__ decay) {
    int idx = blockIdx.x * blockDim.x + threadIdx.x;
    if (idx >= SEQ * HV) return;
    int h = idx & (HV - 1);
    beta[idx] = sigmoidf(b[idx]);
    float xv = a[idx] + dtb[h];
    float sp = (xv > 20.f) ? xv : log1pf(expf(xv));
    decay[idx] = expf(-expf(alog[h]) * sp);
}

// ---------------- sequential delta-rule scan ----------------
// 64 blocks: head = bid/4, column-group (16 cols) = bid%4. 256 threads:
// vloc = tid/16, lane-group g = tid%16 owns rows r = g + 16*i.
__global__ void scan_kernel(const float* __restrict__ qn, const float* __restrict__ kn,
                            const float* __restrict__ qkv,
                            const float* __restrict__ decay, const float* __restrict__ beta,
                            const float* __restrict__ state_in,
                            float* __restrict__ o, float* __restrict__ state_out) {
    int h  = blockIdx.x >> 2;
    int cg = blockIdx.x & 3;
    int tid  = threadIdx.x;
    int vloc = tid >> 4;
    int g    = tid & 15;
    int v    = cg * 16 + vloc;
    __shared__ float ks[64], qs[64], vs[64], sc[2];
    float Sreg[4];
    #pragma unroll
    for (int i = 0; i < 4; i++) {
        int r = g + 16*i;
        Sreg[i] = state_in[(long)h * DK * DV + (long)r * DV + v];
    }
    for (int s = 0; s < SEQ; s++) {
        if (tid < 64)        ks[tid]       = kn[(long)s * VALD + h*64 + tid];
        else if (tid < 128)  qs[tid - 64]  = qn[(long)s * VALD + h*64 + (tid - 64)];
        else if (tid < 192)  vs[tid - 128] = qkv[(long)s * CONVD + 2*KEYD + h*64 + (tid - 128)];
        else if (tid == 192) sc[0] = decay[s * HV + h];
        else if (tid == 193) sc[1] = beta[s * HV + h];
        __syncthreads();
        float dec = sc[0], bet = sc[1], vv = vs[v];
        float kr[4], qr[4];
        #pragma unroll
        for (int i = 0; i < 4; i++) { kr[i] = ks[g + 16*i]; qr[i] = qs[g + 16*i]; }
        float pm = 0.f;
        #pragma unroll
        for (int i = 0; i < 4; i++) { Sreg[i] *= dec; pm += kr[i] * Sreg[i]; }
        #pragma unroll
        for (int off = 8; off > 0; off >>= 1) pm += __shfl_xor_sync(0xffffffffu, pm, off);
        float delta = (vv - pm) * bet;
        float po = 0.f;
        #pragma unroll
        for (int i = 0; i < 4; i++) { Sreg[i] += kr[i] * delta; po += qr[i] * Sreg[i]; }
        #pragma unroll
        for (int off = 8; off > 0; off >>= 1) po += __shfl_xor_sync(0xffffffffu, po, off);
        if (g == 0) o[(long)s * VALD + h*64 + v] = po;
        __syncthreads();
    }
    #pragma unroll
    for (int i = 0; i < 4; i++) {
        int r = g + 16*i;
        state_out[(long)h * DK * DV + (long)r * DV + v] = Sreg[i];
    }
}

// ---------------- gated rms-norm over DV with silu(z) gate ----------------
__global__ void gated_norm_kernel(float* __restrict__ o, const float* __restrict__ z,
                                  const float* __restrict__ nw) {
    int gw = blockIdx.x * 8 + (threadIdx.x >> 5);
    int lane = threadIdx.x & 31;
    int s = gw >> 4, h = gw & 15;
    long base = (long)s * VALD + h * 64;
    float o0 = o[base + lane], o1 = o[base + 32 + lane];
    float ss = warp_reduce(o0*o0 + o1*o1);
    float r = rsqrtf(ss / 64.f + 1e-6f);
    float w0 = 1.f + nw[h*64 + lane], w1 = 1.f + nw[h*64 + 32 + lane];
    float z0 = z[base + lane], z1 = z[base + 32 + lane];
    o[base + lane]      = o0 * r * w0 * siluf(z0);
    o[base + 32 + lane] = o1 * r * w1 * siluf(z1);
}

// ---------------- elementwise adds ----------------
__global__ void add_kernel(const float* __restrict__ a, const float* __restrict__ b,
                           float* __restrict__ y, long n) {
    long i = (long)blockIdx.x * blockDim.x + threadIdx.x;
    if (i < n) y[i] = a[i] + b[i];
}

// ---------------- router: logits, softmax, top-2 ----------------
__global__ void router_kernel(const float* __restrict__ t, const float* __restrict__ rw,
                              int* __restrict__ topi, float* __restrict__ topw) {
    int tok = blockIdx.x;
    int wrp = threadIdx.x >> 5, lane = threadIdx.x & 31;
    __shared__ float lg[NE];
    const float* row = t + (long)tok * DMODEL;
    const float* wr = rw + (long)wrp * DMODEL;
    float s = 0.f;
    for (int d = lane; d < DMODEL; d += 32) s += row[d] * wr[d];
    s = warp_reduce(s);
    if (lane == 0) lg[wrp] = s;
    __syncthreads();
    if (threadIdx.x == 0) {
        float mx = -1e30f;
        #pragma unroll
        for (int e = 0; e < NE; e++) mx = fmaxf(mx, lg[e]);
        float ex[NE]; float sum = 0.f;
        #pragma unroll
        for (int e = 0; e < NE; e++) { ex[e] = expf(lg[e] - mx); sum += ex[e]; }
        int b0 = 0; float p0 = -1.f;
        #pragma unroll
        for (int e = 0; e < NE; e++) if (ex[e] > p0) { p0 = ex[e]; b0 = e; }
        int b1 = -1; float p1 = -1.f;
        #pragma unroll
        for (int e = 0; e < NE; e++) if (e != b0 && ex[e] > p1) { p1 = ex[e]; b1 = e; }
        float tot = p0 + p1;
        topi[tok*2]     = b0;  topi[tok*2 + 1] = b1;
        topw[tok*2]     = p0 / tot;
        topw[tok*2 + 1] = p1 / tot;
    }
}

__global__ void zero_kernel(float* __restrict__ routed, int* __restrict__ cnt) {
    long i = (long)blockIdx.x * blockDim.x + threadIdx.x;
    if (i < (long)SEQ * DMODEL) routed[i] = 0.f;
    if (i < NE) cnt[i] = 0;
}

__global__ void build_kernel(const int* __restrict__ topi, const float* __restrict__ topw,
                             int* __restrict__ cnt, int* __restrict__ list,
                             float* __restrict__ lw) {
    int tok = blockIdx.x * blockDim.x + threadIdx.x;
    if (tok >= SEQ) return;
    #pragma unroll
    for (int j = 0; j < TOPK; j++) {
        int e = topi[tok*2 + j];
        int pos = atomicAdd(&cnt[e], 1);
        list[e * SEQ + pos] = tok;
        lw[e * SEQ + pos]   = topw[tok*2 + j];
    }
}

__global__ void moe_act_kernel(const float* __restrict__ gu, const int* __restrict__ cnt,
                               float* __restrict__ act) {
    int e = blockIdx.z;
    int idx = blockIdx.x * blockDim.x + threadIdx.x;
    int row = idx >> 9;         // /512
    int i   = idx & 511;
    if (row >= cnt[e]) return;
    long b = (long)e * SEQ * 1024 + (long)row * 1024;
    float gt = gu[b + i], up = gu[b + 512 + i];
    act[(long)e * SEQ * IMOE + (long)row * IMOE + i] = siluf(gt) * up;
}

__global__ void act2_kernel(float* __restrict__ sg, const float* __restrict__ su) {
    long i = (long)blockIdx.x * blockDim.x + threadIdx.x;
    if (i >= (long)SEQ * VALD) return;
    float g = sg[i];
    sg[i] = siluf(g) * su[i];
}

__global__ void gate_kernel(const float* __restrict__ t, const float* __restrict__ wg,
                            float* __restrict__ gate) {
    int tok = blockIdx.x * 8 + (threadIdx.x >> 5);
    int lane = threadIdx.x & 31;
    const float* row = t + (long)tok * DMODEL;
    float s = 0.f;
    for (int d = lane; d < DMODEL; d += 32) s += row[d] * wg[d];
    s = warp_reduce(s);
    if (lane == 0) gate[tok] = sigmoidf(s);
}

__global__ void final_kernel(const float* __restrict__ x2, const float* __restrict__ routed,
                             const float* __restrict__ sh, const float* __restrict__ gate,
                             float* __restrict__ out) {
    long i = (long)blockIdx.x * blockDim.x + threadIdx.x;
    if (i >= (long)SEQ * DMODEL) return;
    int row = (int)(i >> 10);
    out[i] = x2[i] + routed[i] + sh[i] * gate[row];
}

__global__ void conv_state_out_kernel(const float* __restrict__ qkvp, float* __restrict__ out) {
    int i = blockIdx.x * blockDim.x + threadIdx.x;
    if (i >= (KW-1) * CONVD) return;
    out[i] = qkvp[(long)(SEQ - (KW-1)) * CONVD + i];
}

// ---------------- host launch ----------------
extern "C" void kernel_launch(void* const* d_in, const int* in_sizes, int n_in,
                              void* d_out, int out_size) {
    const float* x        = (const float*)d_in[0];
    const float* state    = (const float*)d_in[1];
    const float* cstate   = (const float*)d_in[2];
    const float* Wqkv     = (const float*)d_in[3];
    const float* Wz       = (const float*)d_in[4];
    const float* Wa       = (const float*)d_in[5];
    const float* Wb       = (const float*)d_in[6];
    const float* convW    = (const float*)d_in[7];
    const float* dt_bias  = (const float*)d_in[8];
    const float* A_log    = (const float*)d_in[9];
    const float* norm_w   = (const float*)d_in[10];
    const float* Wout     = (const float*)d_in[11];
    const float* routerW  = (const float*)d_in[12];
    const float* Wegu     = (const float*)d_in[13];
    const float* Wed      = (const float*)d_in[14];
    const float* Wsg      = (const float*)d_in[15];
    const float* Wsu      = (const float*)d_in[16];
    const float* Wsd      = (const float*)d_in[17];
    const float* Wseg     = (const float*)d_in[18];
    const float* attn_nw  = (const float*)d_in[19];
    const float* ffn_nw   = (const float*)d_in[20];
    float* out = (float*)d_out;

    float *ph, *pqkvp, *pqkv, *pz, *pa, *pb, *pqn, *pkn, *pbeta, *pdecay, *po;
    float *pattn, *px2, *pt, *ptopw, *plw, *pgu, *pact, *prouted, *psg, *psu, *psh, *pgate;
    int *ptopi, *pcnt, *plist;
    cudaGetSymbolAddress((void**)&ph,     g_h);
    cudaGetSymbolAddress((void**)&pqkvp,  g_qkvp);
    cudaGetSymbolAddress((void**)&pqkv,   g_qkv);
    cudaGetSymbolAddress((void**)&pz,     g_z);
    cudaGetSymbolAddress((void**)&pa,     g_a);
    cudaGetSymbolAddress((void**)&pb,     g_b);
    cudaGetSymbolAddress((void**)&pqn,    g_qn);
    cudaGetSymbolAddress((void**)&pkn,    g_kn);
    cudaGetSymbolAddress((void**)&pbeta,  g_beta);
    cudaGetSymbolAddress((void**)&pdecay, g_decay);
    cudaGetSymbolAddress((void**)&po,     g_o);
    cudaGetSymbolAddress((void**)&pattn,  g_attn);
    cudaGetSymbolAddress((void**)&px2,    g_x2);
    cudaGetSymbolAddress((void**)&pt,     g_t);
    cudaGetSymbolAddress((void**)&ptopi,  g_topi);
    cudaGetSymbolAddress((void**)&ptopw,  g_topw);
    cudaGetSymbolAddress((void**)&pcnt,   g_cnt);
    cudaGetSymbolAddress((void**)&plist,  g_list);
    cudaGetSymbolAddress((void**)&plw,    g_lw);
    cudaGetSymbolAddress((void**)&pgu,    g_gu);
    cudaGetSymbolAddress((void**)&pact,   g_act);
    cudaGetSymbolAddress((void**)&prouted,g_routed);
    cudaGetSymbolAddress((void**)&psg,    g_sg);
    cudaGetSymbolAddress((void**)&psu,    g_su);
    cudaGetSymbolAddress((void**)&psh,    g_sh);
    cudaGetSymbolAddress((void**)&pgate,  g_gate);

    dim3 blk(256);

    // 1. attention rms norm
    rmsnorm_kernel<<<SEQ, 256>>>(x, attn_nw, ph);

    // 2. projections  h@Wqkv, h@Wz, h@Wa, h@Wb
    gemm_kernel<false,false,false><<<dim3(CONVD/64, SEQ/64, 1), blk>>>(
        ph, Wqkv, pqkvp, SEQ, CONVD, DMODEL, 0,0,0, nullptr,nullptr,nullptr,0);
    gemm_kernel<false,false,false><<<dim3(VALD/64, SEQ/64, 1), blk>>>(
        ph, Wz, pz, SEQ, VALD, DMODEL, 0,0,0, nullptr,nullptr,nullptr,0);
    gemm_kernel<false,false,false><<<dim3(1, SEQ/64, 1), blk>>>(
        ph, Wa, pa, SEQ, HV, DMODEL, 0,0,0, nullptr,nullptr,nullptr,0);
    gemm_kernel<false,false,false><<<dim3(1, SEQ/64, 1), blk>>>(
        ph, Wb, pb, SEQ, HV, DMODEL, 0,0,0, nullptr,nullptr,nullptr,0);

    // new conv_state = last 3 raw qkv rows
    conv_state_out_kernel<<<((KW-1)*CONVD + 255)/256, 256>>>(pqkvp, out + OUT_CONV_OFF);

    // 3. depthwise conv + silu
    conv_silu_kernel<<<(SEQ*CONVD + 255)/256, 256>>>(pqkvp, cstate, convW, pqkv);

    // 4. l2norm q,k + repeat;  beta/decay
    l2norm_kernel<<<SEQ*16/8, 256>>>(pqkv, pqn, pkn);
    decay_beta_kernel<<<(SEQ*HV + 255)/256, 256>>>(pa, pb, dt_bias, A_log, pbeta, pdecay);

    // 5. sequential scan (writes o and final state)
    scan_kernel<<<64, 256>>>(pqn, pkn, pqkv, pdecay, pbeta, state, po, out + OUT_STATE_OFF);

    // 6. gated rms norm with silu(z)
    gated_norm_kernel<<<SEQ*16/8, 256>>>(po, pz, norm_w);

    // 7. out projection + residual
    gemm_kernel<false,false,false><<<dim3(DMODEL/64, SEQ/64, 1), blk>>>(
        po, Wout, pattn, SEQ, DMODEL, VALD, 0,0,0, nullptr,nullptr,nullptr,0);
    add_kernel<<<(SEQ*DMODEL + 255)/256, 256>>>(x, pattn, px2, (long)SEQ*DMODEL);

    // 8. ffn rms norm
    rmsnorm_kernel<<<SEQ, 256>>>(px2, ffn_nw, pt);

    // 9. router + gather lists
    router_kernel<<<SEQ, 256>>>(pt, routerW, ptopi, ptopw);
    zero_kernel<<<(SEQ*DMODEL + 255)/256, 256>>>(prouted, pcnt);
    build_kernel<<<(SEQ + 255)/256, 256>>>(ptopi, ptopw, pcnt, plist, plw);

    // 10. routed experts: gather-GEMM gate_up, act, down-GEMM scatter
    gemm_kernel<true,true,false><<<dim3(1024/64, SEQ/64, NE), blk>>>(
        pt, Wegu, pgu, SEQ, 2*IMOE, DMODEL,
        0, (long)2*IMOE*DMODEL, (long)SEQ*1024, plist, pcnt, plw, SEQ);
    moe_act_kernel<<<dim3(SEQ*IMOE/256, 1, NE), 256>>>(pgu, pcnt, pact);
    gemm_kernel<true,false,true><<<dim3(DMODEL/64, SEQ/64, NE), blk>>>(
        pact, Wed, prouted, SEQ, DMODEL, IMOE,
        (long)SEQ*IMOE, (long)DMODEL*IMOE, 0, plist, pcnt, plw, SEQ);

    // 11. shared expert
    gemm_kernel<false,false,false><<<dim3(VALD/64, SEQ/64, 1), blk>>>(
        pt, Wsg, psg, SEQ, VALD, DMODEL, 0,0,0, nullptr,nullptr,nullptr,0);
    gemm_kernel<false,false,false><<<dim3(VALD/64, SEQ/64, 1), blk>>>(
        pt, Wsu, psu, SEQ, VALD, DMODEL, 0,0,0, nullptr,nullptr,nullptr,0);
    act2_kernel<<<(SEQ*VALD + 255)/256, 256>>>(psg, psu);
    gemm_kernel<false,false,false><<<dim3(DMODEL/64, SEQ/64, 1), blk>>>(
        psg, Wsd, psh, SEQ, DMODEL, VALD, 0,0,0, nullptr,nullptr,nullptr,0);
    gate_kernel<<<SEQ/8, 256>>>(pt, Wseg, pgate);

    // 12. final combine
    final_kernel<<<(SEQ*DMODEL + 255)/256, 256>>>(px2, prouted, psh, pgate, out + OUT_X_OFF);
}

// round 2
// speedup vs baseline: 1.4147x; 1.4147x over previous
#include <cuda_runtime.h>
#include <cuda_bf16.h>
#include <math.h>

// ---------------- problem constants ----------------
#define SEQ     2048
#define DMODEL  1024
#define HKN     8
#define DK      64
#define HV      16
#define DV      64
#define KEYD    512            // HK*DK
#define VALD    1024           // HV*DV
#define CONVD   2048           // 2*KEYD + VALD
#define KW      4
#define NE      8
#define TOPK    2
#define IMOE    512

// output layout in d_out (floats): x | state | conv_state
#define OUT_X_OFF     0
#define OUT_STATE_OFF (SEQ*DMODEL)                 // 2097152
#define OUT_CONV_OFF  (OUT_STATE_OFF + HV*DK*DV)   // 2162688

// ---------------- scratch (device globals; no allocs allowed) ----------------
__device__ float g_h    [SEQ*DMODEL];
__device__ float g_qkvp [SEQ*CONVD];
__device__ float g_qkv  [SEQ*CONVD];
__device__ float g_z    [SEQ*VALD];
__device__ float g_qn   [SEQ*VALD];
__device__ float g_kn   [SEQ*VALD];
__device__ float g_beta [SEQ*HV];
__device__ float g_decay[SEQ*HV];
__device__ float g_o    [SEQ*VALD];
__device__ float g_attn [SEQ*DMODEL];
__device__ float g_x2   [SEQ*DMODEL];
__device__ float g_t    [SEQ*DMODEL];
__device__ int   g_topi [SEQ*TOPK];
__device__ float g_topw [SEQ*TOPK];
__device__ int   g_cnt  [NE];
__device__ int   g_list [NE*SEQ];
__device__ float g_lw   [NE*SEQ];
__device__ float g_gu   [(long)NE*SEQ*1024];
__device__ float g_act  [(long)NE*SEQ*IMOE];
__device__ float g_routed[SEQ*DMODEL];
__device__ float g_sg   [SEQ*VALD];
__device__ float g_su   [SEQ*VALD];
__device__ float g_sh   [SEQ*DMODEL];
__device__ float g_gate [SEQ];

// ---------------- helpers ----------------
__device__ __forceinline__ float warp_reduce(float v) {
    #pragma unroll
    for (int o = 16; o > 0; o >>= 1) v += __shfl_xor_sync(0xffffffffu, v, o);
    return v;
}
__device__ __forceinline__ float siluf(float x) { return x / (1.f + expf(-x)); }
__device__ __forceinline__ float sigmoidf(float x) { return 1.f / (1.f + expf(-x)); }

__device__ __forceinline__ void mma_bf16(float* c, const unsigned* a, const unsigned* b) {
    asm volatile(
        "mma.sync.aligned.m16n8k16.row.col.f32.bf16.bf16.f32 "
        "{%0,%1,%2,%3}, {%4,%5,%6,%7}, {%8,%9}, {%0,%1,%2,%3};\n"
        : "+f"(c[0]), "+f"(c[1]), "+f"(c[2]), "+f"(c[3])
        : "r"(a[0]), "r"(a[1]), "r"(a[2]), "r"(a[3]), "r"(b[0]), "r"(b[1]));
}

// split fp32 -> bf16 hi + bf16 lo
__device__ __forceinline__ void split_bf16(float v, __nv_bfloat16& hi, __nv_bfloat16& lo) {
    hi = __float2bfloat16(v);
    lo = __float2bfloat16(v - __bfloat162float(hi));
}

// ---------------- rms norm (row = 1024) ----------------
__global__ void rmsnorm_kernel(const float* __restrict__ x, const float* __restrict__ w,
                               float* __restrict__ y) {
    int row = blockIdx.x;
    int tid = threadIdx.x;
    const float* xr = x + (long)row * DMODEL;
    float v[4]; float ss = 0.f;
    #pragma unroll
    for (int i = 0; i < 4; i++) { v[i] = xr[tid + 256*i]; ss += v[i]*v[i]; }
    ss = warp_reduce(ss);
    __shared__ float sm[8];
    __shared__ float rtot;
    if ((tid & 31) == 0) sm[tid >> 5] = ss;
    __syncthreads();
    if (tid == 0) {
        float t2 = 0.f;
        #pragma unroll
        for (int i = 0; i < 8; i++) t2 += sm[i];
        rtot = rsqrtf(t2 / (float)DMODEL + 1e-6f);
    }
    __syncthreads();
    float r = rtot;
    float* yr = y + (long)row * DMODEL;
    #pragma unroll
    for (int i = 0; i < 4; i++)
        yr[tid + 256*i] = v[i] * r * (1.f + w[tid + 256*i]);
}

// rmsnorm of (x + add): writes xsum = x+add and y = rmsnorm(xsum)*(1+w)
__global__ void rmsnorm_add_kernel(const float* __restrict__ x, const float* __restrict__ add,
                                   const float* __restrict__ w,
                                   float* __restrict__ xsum, float* __restrict__ y) {
    int row = blockIdx.x;
    int tid = threadIdx.x;
    const float* xr = x + (long)row * DMODEL;
    const float* ar = add + (long)row * DMODEL;
    float v[4]; float ss = 0.f;
    #pragma unroll
    for (int i = 0; i < 4; i++) { v[i] = xr[tid + 256*i] + ar[tid + 256*i]; ss += v[i]*v[i]; }
    ss = warp_reduce(ss);
    __shared__ float sm[8];
    __shared__ float rtot;
    if ((tid & 31) == 0) sm[tid >> 5] = ss;
    __syncthreads();
    if (tid == 0) {
        float t2 = 0.f;
        #pragma unroll
        for (int i = 0; i < 8; i++) t2 += sm[i];
        rtot = rsqrtf(t2 / (float)DMODEL + 1e-6f);
    }
    __syncthreads();
    float r = rtot;
    float* xo = xsum + (long)row * DMODEL;
    float* yr = y + (long)row * DMODEL;
    #pragma unroll
    for (int i = 0; i < 4; i++) {
        xo[tid + 256*i] = v[i];
        yr[tid + 256*i] = v[i] * r * (1.f + w[tid + 256*i]);
    }
}

// ---------------- tensor-core GEMM 128x64x32, bf16 3-split (fp32-accurate) ----
// C[M,N] = A[M,K] * B ; BT: B is (N,K) row-major, else (K,N) row-major.
// AGATHER: A rows via gIdx list. CSCATTER: atomic scatter into C[tok,n]*w.
#define SA 40   // smem stride (halves) for k dimension
template<bool BT, bool AGATHER, bool CSCATTER>
__global__ void __launch_bounds__(256, 2) gemm_kernel(
                            const float* __restrict__ Abase,
                            const float* __restrict__ Bbase,
                            float* __restrict__ Cbase,
                            int M, int N, int K,
                            long aStride, long bStride, long cStride,
                            const int* __restrict__ gIdx,
                            const int* __restrict__ gCnt,
                            const float* __restrict__ gW,
                            int gCap) {
    const int e = blockIdx.z;
    const float* A = Abase + (long)e * aStride;
    const float* B = Bbase + (long)e * bStride;
    float* C = Cbase + (long)e * cStride;

    int Meff = M;
    const int* lst = nullptr;
    const float* wl = nullptr;
    if (AGATHER || CSCATTER) {
        Meff = gCnt[e];
        lst = gIdx + e * gCap;
        wl  = gW  + e * gCap;
    }
    int m0 = blockIdx.y * 128;
    int n0 = blockIdx.x * 64;
    if (m0 >= Meff) return;

    __shared__ __nv_bfloat16 Ah[128*SA], Al[128*SA], Bh[64*SA], Bl[64*SA];

    int tid = threadIdx.x;
    int wid = tid >> 5, lane = tid & 31;
    int g = lane >> 2, q = lane & 3;
    int mbase = (wid >> 1) * 32;     // 0,32,64,96
    int nbase = (wid & 1) * 32;      // 0,32

    float acc[2][4][4];
    #pragma unroll
    for (int a = 0; a < 2; a++)
        #pragma unroll
        for (int b = 0; b < 4; b++)
            #pragma unroll
            for (int c = 0; c < 4; c++) acc[a][b][c] = 0.f;

    for (int k0 = 0; k0 < K; k0 += 32) {
        // ---- load A tile 128x32 ----
        #pragma unroll
        for (int j = 0; j < 4; j++) {
            int id = tid + 256*j;          // 0..1023
            int r = id >> 3;
            int kq = (id & 7) * 4;
            float4 v = make_float4(0.f,0.f,0.f,0.f);
            int m = m0 + r;
            if (m < Meff) {
                long gr = AGATHER ? (long)lst[m] : (long)m;
                v = *reinterpret_cast<const float4*>(A + gr * K + k0 + kq);
            }
            __nv_bfloat162 h2, l2;
            __nv_bfloat16 h, l;
            split_bf16(v.x, h, l); h2.x = h; l2.x = l;
            split_bf16(v.y, h, l); h2.y = h; l2.y = l;
            *reinterpret_cast<__nv_bfloat162*>(&Ah[r*SA + kq])     = h2;
            *reinterpret_cast<__nv_bfloat162*>(&Al[r*SA + kq])     = l2;
            split_bf16(v.z, h, l); h2.x = h; l2.x = l;
            split_bf16(v.w, h, l); h2.y = h; l2.y = l;
            *reinterpret_cast<__nv_bfloat162*>(&Ah[r*SA + kq + 2]) = h2;
            *reinterpret_cast<__nv_bfloat162*>(&Al[r*SA + kq + 2]) = l2;
        }
        // ---- load B tile into smem as [n][k] ----
        if (BT) {
            #pragma unroll
            for (int j = 0; j < 2; j++) {
                int id = tid + 256*j;      // 0..511
                int n = id >> 3;
                int kq = (id & 7) * 4;
                float4 v = *reinterpret_cast<const float4*>(B + (long)(n0 + n) * K + k0 + kq);
                __nv_bfloat162 h2, l2;
                __nv_bfloat16 h, l;
                split_bf16(v.x, h, l); h2.x = h; l2.x = l;
                split_bf16(v.y, h, l); h2.y = h; l2.y = l;
                *reinterpret_cast<__nv_bfloat162*>(&Bh[n*SA + kq])     = h2;
                *reinterpret_cast<__nv_bfloat162*>(&Bl[n*SA + kq])     = l2;
                split_bf16(v.z, h, l); h2.x = h; l2.x = l;
                split_bf16(v.w, h, l); h2.y = h; l2.y = l;
                *reinterpret_cast<__nv_bfloat162*>(&Bh[n*SA + kq + 2]) = h2;
                *reinterpret_cast<__nv_bfloat162*>(&Bl[n*SA + kq + 2]) = l2;
            }
        } else {
            #pragma unroll
            for (int j = 0; j < 2; j++) {
                int id = tid + 256*j;      // 0..511
                int kk = id >> 4;          // 0..31
                int nq = (id & 15) * 4;
                float4 v = *reinterpret_cast<const float4*>(B + (long)(k0 + kk) * N + n0 + nq);
                __nv_bfloat16 h, l;
                split_bf16(v.x, h, l); Bh[(nq+0)*SA + kk] = h; Bl[(nq+0)*SA + kk] = l;
                split_bf16(v.y, h, l); Bh[(nq+1)*SA + kk] = h; Bl[(nq+1)*SA + kk] = l;
                split_bf16(v.z, h, l); Bh[(nq+2)*SA + kk] = h; Bl[(nq+2)*SA + kk] = l;
                split_bf16(v.w, h, l); Bh[(nq+3)*SA + kk] = h; Bl[(nq+3)*SA + kk] = l;
            }
        }
        __syncthreads();

        // ---- compute: 2 k-steps of m16n8k16 ----
        #pragma unroll
        for (int ks = 0; ks < 2; ks++) {
            int kb = ks * 16;
            unsigned af[2][2][4];
            #pragma unroll
            for (int mt = 0; mt < 2; mt++) {
                int r = mbase + mt*16 + g;
                int c0 = kb + 2*q;
                af[mt][0][0] = *reinterpret_cast<const unsigned*>(&Ah[r*SA + c0]);
                af[mt][0][1] = *reinterpret_cast<const unsigned*>(&Ah[(r+8)*SA + c0]);
                af[mt][0][2] = *reinterpret_cast<const unsigned*>(&Ah[r*SA + c0 + 8]);
                af[mt][0][3] = *reinterpret_cast<const unsigned*>(&Ah[(r+8)*SA + c0 + 8]);
                af[mt][1][0] = *reinterpret_cast<const unsigned*>(&Al[r*SA + c0]);
                af[mt][1][1] = *reinterpret_cast<const unsigned*>(&Al[(r+8)*SA + c0]);
                af[mt][1][2] = *reinterpret_cast<const unsigned*>(&Al[r*SA + c0 + 8]);
                af[mt][1][3] = *reinterpret_cast<const unsigned*>(&Al[(r+8)*SA + c0 + 8]);
            }
            unsigned bfr[4][2][2];
            #pragma unroll
            for (int nt = 0; nt < 4; nt++) {
                int n = nbase + nt*8 + g;
                int c0 = kb + 2*q;
                bfr[nt][0][0] = *reinterpret_cast<const unsigned*>(&Bh[n*SA + c0]);
                bfr[nt][0][1] = *reinterpret_cast<const unsigned*>(&Bh[n*SA + c0 + 8]);
                bfr[nt][1][0] = *reinterpret_cast<const unsigned*>(&Bl[n*SA + c0]);
                bfr[nt][1][1] = *reinterpret_cast<const unsigned*>(&Bl[n*SA + c0 + 8]);
            }
            #pragma unroll
            for (int mt = 0; mt < 2; mt++)
                #pragma unroll
                for (int nt = 0; nt < 4; nt++) {
                    mma_bf16(acc[mt][nt], af[mt][0], bfr[nt][0]);  // hi*hi
                    mma_bf16(acc[mt][nt], af[mt][0], bfr[nt][1]);  // hi*lo
                    mma_bf16(acc[mt][nt], af[mt][1], bfr[nt][0]);  // lo*hi
                }
        }
        __syncthreads();
    }

    // ---- epilogue ----
    #pragma unroll
    for (int mt = 0; mt < 2; mt++) {
        int r0 = m0 + mbase + mt*16 + g;
        int r1 = r0 + 8;
        if (CSCATTER) {
            int tok0 = 0, tok1 = 0; float w0 = 0.f, w1 = 0.f;
            bool ok0 = r0 < Meff, ok1 = r1 < Meff;
            if (ok0) { tok0 = lst[r0]; w0 = wl[r0]; }
            if (ok1) { tok1 = lst[r1]; w1 = wl[r1]; }
            #pragma unroll
            for (int nt = 0; nt < 4; nt++) {
                int col = n0 + nbase + nt*8 + 2*q;
                if (ok0) {
                    atomicAdd(&C[(long)tok0 * N + col],     w0 * acc[mt][nt][0]);
                    atomicAdd(&C[(long)tok0 * N + col + 1], w0 * acc[mt][nt][1]);
                }
                if (ok1) {
                    atomicAdd(&C[(long)tok1 * N + col],     w1 * acc[mt][nt][2]);
                    atomicAdd(&C[(long)tok1 * N + col + 1], w1 * acc[mt][nt][3]);
                }
            }
        } else {
            bool ok0 = r0 < Meff, ok1 = r1 < Meff;
            #pragma unroll
            for (int nt = 0; nt < 4; nt++) {
                int col = n0 + nbase + nt*8 + 2*q;
                if (ok0) *reinterpret_cast<float2*>(&C[(long)r0 * N + col]) =
                    make_float2(acc[mt][nt][0], acc[mt][nt][1]);
                if (ok1) *reinterpret_cast<float2*>(&C[(long)r1 * N + col]) =
                    make_float2(acc[mt][nt][2], acc[mt][nt][3]);
            }
        }
    }
}

// ---------------- fused a/b projection -> beta/decay --------------------
__global__ void ab_kernel(const float* __restrict__ h,
                          const float* __restrict__ Wa, const float* __restrict__ Wb,
                          const float* __restrict__ dtb, const float* __restrict__ alog,
                          float* __restrict__ beta, float* __restrict__ decay) {
    int tok = blockIdx.x;
    int w = threadIdx.x >> 5, lane = threadIdx.x & 31;
    bool isB = w >= 4;
    int c0 = (w & 3) * 4;
    const float* W = isB ? Wb : Wa;
    const float* hr = h + (long)tok * DMODEL;
    float s0 = 0.f, s1 = 0.f, s2 = 0.f, s3 = 0.f;
    for (int d = lane; d < DMODEL; d += 32) {
        float hv = hr[d];
        const float* wd = W + (long)d * HV + c0;
        s0 += hv * wd[0]; s1 += hv * wd[1]; s2 += hv * wd[2]; s3 += hv * wd[3];
    }
    s0 = warp_reduce(s0); s1 = warp_reduce(s1);
    s2 = warp_reduce(s2); s3 = warp_reduce(s3);
    if (lane == 0) {
        float sv[4] = {s0, s1, s2, s3};
        #pragma unroll
        for (int i = 0; i < 4; i++) {
            int hc = c0 + i, idx = tok * HV + hc;
            if (isB) beta[idx] = sigmoidf(sv[i]);
            else {
                float xv = sv[i] + dtb[hc];
                float sp = (xv > 20.f) ? xv : log1pf(expf(xv));
                decay[idx] = expf(-expf(alog[hc]) * sp);
            }
        }
    }
}

// ---------------- depthwise causal conv (KW=4) + silu ----------------
__global__ void conv_silu_kernel(const float* __restrict__ qkvp,
                                 const float* __restrict__ conv_state,
                                 const float* __restrict__ w,
                                 float* __restrict__ out) {
    long idx = (long)blockIdx.x * blockDim.x + threadIdx.x;
    if (idx >= (long)SEQ * CONVD) return;
    int s = (int)(idx / CONVD);
    int c = (int)(idx % CONVD);
    float acc = 0.f;
    #pragma unroll
    for (int j = 0; j < KW; j++) {
        int p = s + j;
        float xv = (p < KW-1) ? conv_state[(long)p * CONVD + c]
                              : qkvp[(long)(p - (KW-1)) * CONVD + c];
        acc += xv * w[c * KW + j];
    }
    out[idx] = siluf(acc);
}

// ---------------- l2norm of q,k heads + repeat to HV + q scale ----------------
__global__ void l2norm_kernel(const float* __restrict__ qkv,
                              float* __restrict__ qn, float* __restrict__ kn) {
    int gw = blockIdx.x * 8 + (threadIdx.x >> 5);
    int lane = threadIdx.x & 31;
    int s = gw >> 4;
    int rr = gw & 15;
    bool isq = rr < 8;
    int hk = isq ? rr : rr - 8;
    long base = (long)s * CONVD + (isq ? 0 : KEYD) + hk * 64;
    float v0 = qkv[base + lane];
    float v1 = qkv[base + 32 + lane];
    float ss = warp_reduce(v0*v0 + v1*v1);
    float r = rsqrtf(ss + 1e-6f);
    float sc = isq ? 0.125f : 1.f;    // DK^-0.5 = 1/8 for q
    float o0 = v0 * r * sc, o1 = v1 * r * sc;
    float* dst = isq ? qn : kn;
    long b0 = (long)s * VALD + (2*hk) * 64;
    long b1 = (long)s * VALD + (2*hk + 1) * 64;
    dst[b0 + lane] = o0;       dst[b0 + 32 + lane] = o1;
    dst[b1 + lane] = o0;       dst[b1 + 32 + lane] = o1;
}

// ---------------- sequential delta-rule scan ----------------
__global__ void scan_kernel(const float* __restrict__ qn, const float* __restrict__ kn,
                            const float* __restrict__ qkv,
                            const float* __restrict__ decay, const float* __restrict__ beta,
                            const float* __restrict__ state_in,
                            float* __restrict__ o, float* __restrict__ state_out) {
    int h  = blockIdx.x >> 2;
    int cg = blockIdx.x & 3;
    int tid  = threadIdx.x;
    int vloc = tid >> 4;
    int g    = tid & 15;
    int v    = cg * 16 + vloc;
    __shared__ float ks[64], qs[64], vs[64], sc[2];
    float Sreg[4];
    #pragma unroll
    for (int i = 0; i < 4; i++) {
        int r = g + 16*i;
        Sreg[i] = state_in[(long)h * DK * DV + (long)r * DV + v];
    }
    for (int s = 0; s < SEQ; s++) {
        if (tid < 64)        ks[tid]       = kn[(long)s * VALD + h*64 + tid];
        else if (tid < 128)  qs[tid - 64]  = qn[(long)s * VALD + h*64 + (tid - 64)];
        else if (tid < 192)  vs[tid - 128] = qkv[(long)s * CONVD + 2*KEYD + h*64 + (tid - 128)];
        else if (tid == 192) sc[0] = decay[s * HV + h];
        else if (tid == 193) sc[1] = beta[s * HV + h];
        __syncthreads();
        float dec = sc[0], bet = sc[1], vv = vs[v];
        float kr[4], qr[4];
        #pragma unroll
        for (int i = 0; i < 4; i++) { kr[i] = ks[g + 16*i]; qr[i] = qs[g + 16*i]; }
        float pm = 0.f;
        #pragma unroll
        for (int i = 0; i < 4; i++) { Sreg[i] *= dec; pm += kr[i] * Sreg[i]; }
        #pragma unroll
        for (int off = 8; off > 0; off >>= 1) pm += __shfl_xor_sync(0xffffffffu, pm, off);
        float delta = (vv - pm) * bet;
        float po = 0.f;
        #pragma unroll
        for (int i = 0; i < 4; i++) { Sreg[i] += kr[i] * delta; po += qr[i] * Sreg[i]; }
        #pragma unroll
        for (int off = 8; off > 0; off >>= 1) po += __shfl_xor_sync(0xffffffffu, po, off);
        if (g == 0) o[(long)s * VALD + h*64 + v] = po;
        __syncthreads();
    }
    #pragma unroll
    for (int i = 0; i < 4; i++) {
        int r = g + 16*i;
        state_out[(long)h * DK * DV + (long)r * DV + v] = Sreg[i];
    }
}

// ---------------- gated rms-norm over DV with silu(z) gate ----------------
__global__ void gated_norm_kernel(float* __restrict__ o, const float* __restrict__ z,
                                  const float* __restrict__ nw) {
    int gw = blockIdx.x * 8 + (threadIdx.x >> 5);
    int lane = threadIdx.x & 31;
    int s = gw >> 4, h = gw & 15;
    long base = (long)s * VALD + h * 64;
    float o0 = o[base + lane], o1 = o[base + 32 + lane];
    float ss = warp_reduce(o0*o0 + o1*o1);
    float r = rsqrtf(ss / 64.f + 1e-6f);
    float w0 = 1.f + nw[h*64 + lane], w1 = 1.f + nw[h*64 + 32 + lane];
    float z0 = z[base + lane], z1 = z[base + 32 + lane];
    o[base + lane]      = o0 * r * w0 * siluf(z0);
    o[base + 32 + lane] = o1 * r * w1 * siluf(z1);
}

// ---------------- router: logits, softmax, top-2 ----------------
__global__ void router_kernel(const float* __restrict__ t, const float* __restrict__ rw,
                              int* __restrict__ topi, float* __restrict__ topw) {
    int tok = blockIdx.x;
    int wrp = threadIdx.x >> 5, lane = threadIdx.x & 31;
    __shared__ float lg[NE];
    const float* row = t + (long)tok * DMODEL;
    const float* wr = rw + (long)wrp * DMODEL;
    float s = 0.f;
    for (int d = lane; d < DMODEL; d += 32) s += row[d] * wr[d];
    s = warp_reduce(s);
    if (lane == 0) lg[wrp] = s;
    __syncthreads();
    if (threadIdx.x == 0) {
        float mx = -1e30f;
        #pragma unroll
        for (int e = 0; e < NE; e++) mx = fmaxf(mx, lg[e]);
        float ex[NE]; float sum = 0.f;
        #pragma unroll
        for (int e = 0; e < NE; e++) { ex[e] = expf(lg[e] - mx); sum += ex[e]; }
        int b0 = 0; float p0 = -1.f;
        #pragma unroll
        for (int e = 0; e < NE; e++) if (ex[e] > p0) { p0 = ex[e]; b0 = e; }
        int b1 = -1; float p1 = -1.f;
        #pragma unroll
        for (int e = 0; e < NE; e++) if (e != b0 && ex[e] > p1) { p1 = ex[e]; b1 = e; }
        float tot = p0 + p1;
        topi[tok*2]     = b0;  topi[tok*2 + 1] = b1;
        topw[tok*2]     = p0 / tot;
        topw[tok*2 + 1] = p1 / tot;
    }
}

__global__ void zero_kernel(float* __restrict__ routed, int* __restrict__ cnt) {
    long i = (long)blockIdx.x * blockDim.x + threadIdx.x;
    if (i < (long)SEQ * DMODEL) routed[i] = 0.f;
    if (i < NE) cnt[i] = 0;
}

__global__ void build_kernel(const int* __restrict__ topi, const float* __restrict__ topw,
                             int* __restrict__ cnt, int* __restrict__ list,
                             float* __restrict__ lw) {
    int tok = blockIdx.x * blockDim.x + threadIdx.x;
    if (tok >= SEQ) return;
    #pragma unroll
    for (int j = 0; j < TOPK; j++) {
        int e = topi[tok*2 + j];
        int pos = atomicAdd(&cnt[e], 1);
        list[e * SEQ + pos] = tok;
        lw[e * SEQ + pos]   = topw[tok*2 + j];
    }
}

__global__ void moe_act_kernel(const float* __restrict__ gu, const int* __restrict__ cnt,
                               float* __restrict__ act) {
    int e = blockIdx.z;
    int idx = blockIdx.x * blockDim.x + threadIdx.x;
    int row = idx >> 9;         // /512
    int i   = idx & 511;
    if (row >= cnt[e]) return;
    long b = (long)e * SEQ * 1024 + (long)row * 1024;
    float gt = gu[b + i], up = gu[b + 512 + i];
    act[(long)e * SEQ * IMOE + (long)row * IMOE + i] = siluf(gt) * up;
}

__global__ void act2_kernel(float* __restrict__ sg, const float* __restrict__ su) {
    long i = (long)blockIdx.x * blockDim.x + threadIdx.x;
    if (i >= (long)SEQ * VALD) return;
    float g = sg[i];
    sg[i] = siluf(g) * su[i];
}

__global__ void gate_kernel(const float* __restrict__ t, const float* __restrict__ wg,
                            float* __restrict__ gate) {
    int tok = blockIdx.x * 8 + (threadIdx.x >> 5);
    int lane = threadIdx.x & 31;
    const float* row = t + (long)tok * DMODEL;
    float s = 0.f;
    for (int d = lane; d < DMODEL; d += 32) s += row[d] * wg[d];
    s = warp_reduce(s);
    if (lane == 0) gate[tok] = sigmoidf(s);
}

__global__ void final_kernel(const float* __restrict__ x2, const float* __restrict__ routed,
                             const float* __restrict__ sh, const float* __restrict__ gate,
                             float* __restrict__ out) {
    long i = (long)blockIdx.x * blockDim.x + threadIdx.x;
    if (i >= (long)SEQ * DMODEL) return;
    int row = (int)(i >> 10);
    out[i] = x2[i] + routed[i] + sh[i] * gate[row];
}

__global__ void conv_state_out_kernel(const float* __restrict__ qkvp, float* __restrict__ out) {
    int i = blockIdx.x * blockDim.x + threadIdx.x;
    if (i >= (KW-1) * CONVD) return;
    out[i] = qkvp[(long)(SEQ - (KW-1)) * CONVD + i];
}

// ---------------- host launch ----------------
extern "C" void kernel_launch(void* const* d_in, const int* in_sizes, int n_in,
                              void* d_out, int out_size) {
    const float* x        = (const float*)d_in[0];
    const float* state    = (const float*)d_in[1];
    const float* cstate   = (const float*)d_in[2];
    const float* Wqkv     = (const float*)d_in[3];
    const float* Wz       = (const float*)d_in[4];
    const float* Wa       = (const float*)d_in[5];
    const float* Wb       = (const float*)d_in[6];
    const float* convW    = (const float*)d_in[7];
    const float* dt_bias  = (const float*)d_in[8];
    const float* A_log    = (const float*)d_in[9];
    const float* norm_w   = (const float*)d_in[10];
    const float* Wout     = (const float*)d_in[11];
    const float* routerW  = (const float*)d_in[12];
    const float* Wegu     = (const float*)d_in[13];
    const float* Wed      = (const float*)d_in[14];
    const float* Wsg      = (const float*)d_in[15];
    const float* Wsu      = (const float*)d_in[16];
    const float* Wsd      = (const float*)d_in[17];
    const float* Wseg     = (const float*)d_in[18];
    const float* attn_nw  = (const float*)d_in[19];
    const float* ffn_nw   = (const float*)d_in[20];
    float* out = (float*)d_out;

    float *ph, *pqkvp, *pqkv, *pz, *pqn, *pkn, *pbeta, *pdecay, *po;
    float *pattn, *px2, *pt, *ptopw, *plw, *pgu, *pact, *prouted, *psg, *psu, *psh, *pgate;
    int *ptopi, *pcnt, *plist;
    cudaGetSymbolAddress((void**)&ph,     g_h);
    cudaGetSymbolAddress((void**)&pqkvp,  g_qkvp);
    cudaGetSymbolAddress((void**)&pqkv,   g_qkv);
    cudaGetSymbolAddress((void**)&pz,     g_z);
    cudaGetSymbolAddress((void**)&pqn,    g_qn);
    cudaGetSymbolAddress((void**)&pkn,    g_kn);
    cudaGetSymbolAddress((void**)&pbeta,  g_beta);
    cudaGetSymbolAddress((void**)&pdecay, g_decay);
    cudaGetSymbolAddress((void**)&po,     g_o);
    cudaGetSymbolAddress((void**)&pattn,  g_attn);
    cudaGetSymbolAddress((void**)&px2,    g_x2);
    cudaGetSymbolAddress((void**)&pt,     g_t);
    cudaGetSymbolAddress((void**)&ptopi,  g_topi);
    cudaGetSymbolAddress((void**)&ptopw,  g_topw);
    cudaGetSymbolAddress((void**)&pcnt,   g_cnt);
    cudaGetSymbolAddress((void**)&plist,  g_list);
    cudaGetSymbolAddress((void**)&plw,    g_lw);
    cudaGetSymbolAddress((void**)&pgu,    g_gu);
    cudaGetSymbolAddress((void**)&pact,   g_act);
    cudaGetSymbolAddress((void**)&prouted,g_routed);
    cudaGetSymbolAddress((void**)&psg,    g_sg);
    cudaGetSymbolAddress((void**)&psu,    g_su);
    cudaGetSymbolAddress((void**)&psh,    g_sh);
    cudaGetSymbolAddress((void**)&pgate,  g_gate);

    dim3 blk(256);

    // 1. attention rms norm
    rmsnorm_kernel<<<SEQ, 256>>>(x, attn_nw, ph);

    // 2. projections: h@Wqkv, h@Wz (tensor core); fused a/b -> beta,decay
    gemm_kernel<false,false,false><<<dim3(CONVD/64, SEQ/128, 1), blk>>>(
        ph, Wqkv, pqkvp, SEQ, CONVD, DMODEL, 0,0,0, nullptr,nullptr,nullptr,0);
    gemm_kernel<false,false,false><<<dim3(VALD/64, SEQ/128, 1), blk>>>(
        ph, Wz, pz, SEQ, VALD, DMODEL, 0,0,0, nullptr,nullptr,nullptr,0);
    ab_kernel<<<SEQ, 256>>>(ph, Wa, Wb, dt_bias, A_log, pbeta, pdecay);

    // new conv_state = last 3 raw qkv rows
    conv_state_out_kernel<<<((KW-1)*CONVD + 255)/256, 256>>>(pqkvp, out + OUT_CONV_OFF);

    // 3. depthwise conv + silu
    conv_silu_kernel<<<(SEQ*CONVD + 255)/256, 256>>>(pqkvp, cstate, convW, pqkv);

    // 4. l2norm q,k + repeat
    l2norm_kernel<<<SEQ*16/8, 256>>>(pqkv, pqn, pkn);

    // 5. sequential scan (writes o and final state)
    scan_kernel<<<64, 256>>>(pqn, pkn, pqkv, pdecay, pbeta, state, po, out + OUT_STATE_OFF);

    // 6. gated rms norm with silu(z)
    gated_norm_kernel<<<SEQ*16/8, 256>>>(po, pz, norm_w);

    // 7. out projection; residual fused into ffn rmsnorm
    gemm_kernel<false,false,false><<<dim3(DMODEL/64, SEQ/128, 1), blk>>>(
        po, Wout, pattn, SEQ, DMODEL, VALD, 0,0,0, nullptr,nullptr,nullptr,0);

    // 8. x2 = x + attn ; t = rmsnorm(x2)
    rmsnorm_add_kernel<<<SEQ, 256>>>(x, pattn, ffn_nw, px2, pt);

    // 9. router + gather lists
    router_kernel<<<SEQ, 256>>>(pt, routerW, ptopi, ptopw);
    zero_kernel<<<(SEQ*DMODEL + 255)/256, 256>>>(prouted, pcnt);
    build_kernel<<<(SEQ + 255)/256, 256>>>(ptopi, ptopw, pcnt, plist, plw);

    // 10. routed experts
    gemm_kernel<true,true,false><<<dim3(1024/64, SEQ/128, NE), blk>>>(
        pt, Wegu, pgu, SEQ, 2*IMOE, DMODEL,
        0, (long)2*IMOE*DMODEL, (long)SEQ*1024, plist, pcnt, plw, SEQ);
    moe_act_kernel<<<dim3(SEQ*IMOE/256, 1, NE), 256>>>(pgu, pcnt, pact);
    gemm_kernel<true,false,true><<<dim3(DMODEL/64, SEQ/128, NE), blk>>>(
        pact, Wed, prouted, SEQ, DMODEL, IMOE,
        (long)SEQ*IMOE, (long)DMODEL*IMOE, 0, plist, pcnt, plw, SEQ);

    // 11. shared expert
    gemm_kernel<false,false,false><<<dim3(VALD/64, SEQ/128, 1), blk>>>(
        pt, Wsg, psg, SEQ, VALD, DMODEL, 0,0,0, nullptr,nullptr,nullptr,0);
    gemm_kernel<false,false,false><<<dim3(VALD/64, SEQ/128, 1), blk>>>(
        pt, Wsu, psu, SEQ, VALD, DMODEL, 0,0,0, nullptr,nullptr,nullptr,0);
    act2_kernel<<<(SEQ*VALD + 255)/256, 256>>>(psg, psu);
    gemm_kernel<false,false,false><<<dim3(DMODEL/64, SEQ/128, 1), blk>>>(
        psg, Wsd, psh, SEQ, DMODEL, VALD, 0,0,0, nullptr,nullptr,nullptr,0);
    gate_kernel<<<SEQ/8, 256>>>(pt, Wseg, pgate);

    // 12. final combine
    final_kernel<<<(SEQ*DMODEL + 255)/256, 256>>>(px2, prouted, psh, pgate, out + OUT_X_OFF);
}

// round 3
// speedup vs baseline: 1.7996x; 1.2721x over previous
#include <cuda_runtime.h>
#include <cuda_bf16.h>
#include <math.h>

// ---------------- problem constants ----------------
#define SEQ     2048
#define DMODEL  1024
#define HKN     8
#define DK      64
#define HV      16
#define DV      64
#define KEYD    512
#define VALD    1024
#define CONVD   2048
#define QZD     3072           // CONVD + VALD (fused qkv|z projection)
#define KW      4
#define NE      8
#define TOPK    2
#define IMOE    512

#define OUT_X_OFF     0
#define OUT_STATE_OFF (SEQ*DMODEL)
#define OUT_CONV_OFF  (OUT_STATE_OFF + HV*DK*DV)

// ---------------- scratch ----------------
__device__ float g_h    [SEQ*DMODEL];
__device__ __nv_bfloat16 g_hh[SEQ*DMODEL], g_hl[SEQ*DMODEL];
__device__ float g_qkvz [SEQ*QZD];
__device__ float g_qkv  [SEQ*CONVD];
__device__ float g_qn   [SEQ*VALD];
__device__ float g_kn   [SEQ*VALD];
__device__ float g_beta [SEQ*HV];
__device__ float g_decay[SEQ*HV];
__device__ float g_o    [SEQ*VALD];
__device__ __nv_bfloat16 g_oh[SEQ*VALD], g_ol[SEQ*VALD];
__device__ float g_attn [SEQ*DMODEL];
__device__ float g_x2   [SEQ*DMODEL];
__device__ float g_t    [SEQ*DMODEL];
__device__ __nv_bfloat16 g_th[SEQ*DMODEL], g_tl[SEQ*DMODEL];
__device__ int   g_topi [SEQ*TOPK];
__device__ float g_topw [SEQ*TOPK];
__device__ int   g_cnt  [NE];
__device__ int   g_list [NE*SEQ];
__device__ float g_lw   [NE*SEQ];
__device__ float g_gu   [(long)NE*SEQ*1024];
__device__ __nv_bfloat16 g_acth[(long)NE*SEQ*IMOE], g_actl[(long)NE*SEQ*IMOE];
__device__ float g_routed[SEQ*DMODEL];
__device__ float g_sgu  [SEQ*2048];
__device__ __nv_bfloat16 g_sgh[SEQ*VALD], g_sgl[SEQ*VALD];
__device__ float g_sh   [SEQ*DMODEL];
__device__ float g_gate [SEQ];
// pre-split weights (bf16 hi/lo), B-layout = (N, K) rows
__device__ __nv_bfloat16 g_wqzT_h [QZD*DMODEL],  g_wqzT_l [QZD*DMODEL];    // [qkv|z]^T
__device__ __nv_bfloat16 g_woutT_h[DMODEL*VALD], g_woutT_l[DMODEL*VALD];
__device__ __nv_bfloat16 g_wguT_h [2048*DMODEL], g_wguT_l [2048*DMODEL];   // [sg|su]^T
__device__ __nv_bfloat16 g_wsdT_h [DMODEL*VALD], g_wsdT_l [DMODEL*VALD];
__device__ __nv_bfloat16 g_egu_h  [(long)NE*1024*DMODEL], g_egu_l[(long)NE*1024*DMODEL];
__device__ __nv_bfloat16 g_ed_h   [(long)NE*DMODEL*IMOE], g_ed_l [(long)NE*DMODEL*IMOE];

// ---------------- helpers ----------------
__device__ __forceinline__ float warp_reduce(float v) {
    #pragma unroll
    for (int o = 16; o > 0; o >>= 1) v += __shfl_xor_sync(0xffffffffu, v, o);
    return v;
}
__device__ __forceinline__ float siluf(float x) { return x / (1.f + expf(-x)); }
__device__ __forceinline__ float sigmoidf(float x) { return 1.f / (1.f + expf(-x)); }

__device__ __forceinline__ void mma_bf16(float* c, const unsigned* a, const unsigned* b) {
    asm volatile(
        "mma.sync.aligned.m16n8k16.row.col.f32.bf16.bf16.f32 "
        "{%0,%1,%2,%3}, {%4,%5,%6,%7}, {%8,%9}, {%0,%1,%2,%3};\n"
        : "+f"(c[0]), "+f"(c[1]), "+f"(c[2]), "+f"(c[3])
        : "r"(a[0]), "r"(a[1]), "r"(a[2]), "r"(a[3]), "r"(b[0]), "r"(b[1]));
}
__device__ __forceinline__ void split_bf16(float v, __nv_bfloat16& hi, __nv_bfloat16& lo) {
    hi = __float2bfloat16(v);
    lo = __float2bfloat16(v - __bfloat162float(hi));
}
__device__ __forceinline__ void cp16(void* sptr, const void* gptr, bool valid) {
    unsigned s = (unsigned)__cvta_generic_to_shared(sptr);
    int sz = valid ? 16 : 0;
    asm volatile("cp.async.cg.shared.global [%0], [%1], 16, %2;\n"
                 :: "r"(s), "l"(gptr), "r"(sz));
}

// ---------------- weight prep: transpose + split ----------------
__global__ void tsplit_kernel(const float* __restrict__ W,
                              __nv_bfloat16* __restrict__ oh, __nv_bfloat16* __restrict__ ol,
                              int K, int N) {
    __shared__ float tile[32][33];
    int n0 = blockIdx.x * 32, k0 = blockIdx.y * 32;
    int tx = threadIdx.x & 31, ty = threadIdx.x >> 5;   // ty 0..7
    #pragma unroll
    for (int i = 0; i < 32; i += 8)
        tile[ty + i][tx] = W[(long)(k0 + ty + i) * N + n0 + tx];
    __syncthreads();
    #pragma unroll
    for (int i = 0; i < 32; i += 8) {
        float v = tile[tx][ty + i];
        __nv_bfloat16 h, l; split_bf16(v, h, l);
        long o = (long)(n0 + ty + i) * K + k0 + tx;
        oh[o] = h; ol[o] = l;
    }
}

__global__ void split_kernel(const float* __restrict__ in,
                             __nv_bfloat16* __restrict__ oh, __nv_bfloat16* __restrict__ ol,
                             long n) {
    long i = (long)blockIdx.x * blockDim.x + threadIdx.x;
    if (i >= n) return;
    __nv_bfloat16 h, l; split_bf16(in[i], h, l);
    oh[i] = h; ol[i] = l;
}

// ---------------- rms norm + split ----------------
__global__ void rmsnorm_kernel(const float* __restrict__ x, const float* __restrict__ w,
                               float* __restrict__ y,
                               __nv_bfloat16* __restrict__ yh, __nv_bfloat16* __restrict__ yl) {
    int row = blockIdx.x, tid = threadIdx.x;
    const float* xr = x + (long)row * DMODEL;
    float v[4]; float ss = 0.f;
    #pragma unroll
    for (int i = 0; i < 4; i++) { v[i] = xr[tid + 256*i]; ss += v[i]*v[i]; }
    ss = warp_reduce(ss);
    __shared__ float sm[8]; __shared__ float rtot;
    if ((tid & 31) == 0) sm[tid >> 5] = ss;
    __syncthreads();
    if (tid == 0) {
        float t2 = 0.f;
        #pragma unroll
        for (int i = 0; i < 8; i++) t2 += sm[i];
        rtot = rsqrtf(t2 / (float)DMODEL + 1e-6f);
    }
    __syncthreads();
    float r = rtot;
    #pragma unroll
    for (int i = 0; i < 4; i++) {
        long o = (long)row * DMODEL + tid + 256*i;
        float val = v[i] * r * (1.f + w[tid + 256*i]);
        y[o] = val;
        __nv_bfloat16 h, l; split_bf16(val, h, l);
        yh[o] = h; yl[o] = l;
    }
}

__global__ void rmsnorm_add_kernel(const float* __restrict__ x, const float* __restrict__ add,
                                   const float* __restrict__ w,
                                   float* __restrict__ xsum, float* __restrict__ y,
                                   __nv_bfloat16* __restrict__ yh, __nv_bfloat16* __restrict__ yl) {
    int row = blockIdx.x, tid = threadIdx.x;
    const float* xr = x + (long)row * DMODEL;
    const float* ar = add + (long)row * DMODEL;
    float v[4]; float ss = 0.f;
    #pragma unroll
    for (int i = 0; i < 4; i++) { v[i] = xr[tid + 256*i] + ar[tid + 256*i]; ss += v[i]*v[i]; }
    ss = warp_reduce(ss);
    __shared__ float sm[8]; __shared__ float rtot;
    if ((tid & 31) == 0) sm[tid >> 5] = ss;
    __syncthreads();
    if (tid == 0) {
        float t2 = 0.f;
        #pragma unroll
        for (int i = 0; i < 8; i++) t2 += sm[i];
        rtot = rsqrtf(t2 / (float)DMODEL + 1e-6f);
    }
    __syncthreads();
    float r = rtot;
    #pragma unroll
    for (int i = 0; i < 4; i++) {
        long o = (long)row * DMODEL + tid + 256*i;
        xsum[o] = v[i];
        float val = v[i] * r * (1.f + w[tid + 256*i]);
        y[o] = val;
        __nv_bfloat16 h, l; split_bf16(val, h, l);
        yh[o] = h; yl[o] = l;
    }
}

// ---------------- bf16 tensor-core GEMM 128x64x32, cp.async double buffered ---
#define SA 40
#define STAGE_A (128*SA)
#define STAGE_B (64*SA)
#define GEMM_SMEM ((4*STAGE_A + 4*STAGE_B) * 2)   // bytes = 61440

template<bool AGATHER, bool CSCATTER>
__global__ void __launch_bounds__(256, 2) gemm_bf16_kernel(
        const __nv_bfloat16* __restrict__ Ah_g, const __nv_bfloat16* __restrict__ Al_g,
        const __nv_bfloat16* __restrict__ Bh_g, const __nv_bfloat16* __restrict__ Bl_g,
        float* __restrict__ Cbase,
        int M, int N, int K,
        long aStride, long bStride, long cStride,
        const int* __restrict__ gIdx, const int* __restrict__ gCnt,
        const float* __restrict__ gW, int gCap) {
    extern __shared__ __nv_bfloat16 dsm[];
    __nv_bfloat16* AhS = dsm;
    __nv_bfloat16* AlS = dsm + 2*STAGE_A;
    __nv_bfloat16* BhS = dsm + 4*STAGE_A;
    __nv_bfloat16* BlS = dsm + 4*STAGE_A + 2*STAGE_B;

    const int e = blockIdx.z;
    const __nv_bfloat16* Agh = Ah_g + (long)e * aStride;
    const __nv_bfloat16* Agl = Al_g + (long)e * aStride;
    const __nv_bfloat16* Bgh = Bh_g + (long)e * bStride;
    const __nv_bfloat16* Bgl = Bl_g + (long)e * bStride;
    float* C = Cbase + (long)e * cStride;

    int Meff = M;
    const int* lst = nullptr; const float* wl = nullptr;
    if (AGATHER || CSCATTER) {
        Meff = gCnt[e]; lst = gIdx + e * gCap; wl = gW + e * gCap;
    }
    int m0 = blockIdx.y * 128, n0 = blockIdx.x * 64;
    if (m0 >= Meff) return;

    int tid = threadIdx.x;
    int wid = tid >> 5, lane = tid & 31;
    int g = lane >> 2, q = lane & 3;
    int mbase = (wid >> 1) * 32, nbase = (wid & 1) * 32;

    // load-slot precompute
    const __nv_bfloat16* agp[4]; int adst[4]; bool alo[4], aval[4];
    #pragma unroll
    for (int i = 0; i < 4; i++) {
        int id = tid + 256*i;
        int r = id >> 3, ch = (id >> 1) & 3;
        bool lo = id & 1;
        int m = m0 + r;
        bool vld = m < Meff;
        long grow = 0;
        if (vld) grow = AGATHER ? (long)lst[m] : (long)m;
        agp[i] = (lo ? Agl : Agh) + grow * K + ch * 8;
        adst[i] = r * SA + ch * 8;
        alo[i] = lo; aval[i] = vld;
    }
    const __nv_bfloat16* bgp[2]; int bdst[2]; bool blo[2];
    #pragma unroll
    for (int i = 0; i < 2; i++) {
        int id = tid + 256*i;
        int r = id >> 3, ch = (id >> 1) & 3;
        bool lo = id & 1;
        bgp[i] = (lo ? Bgl : Bgh) + (long)(n0 + r) * K + ch * 8;
        bdst[i] = r * SA + ch * 8;
        blo[i] = lo;
    }

    float acc[2][4][4];
    #pragma unroll
    for (int a = 0; a < 2; a++)
        #pragma unroll
        for (int b = 0; b < 4; b++)
            #pragma unroll
            for (int c = 0; c < 4; c++) acc[a][b][c] = 0.f;

    const int T = K / 32;
    // prologue: stage 0
    {
        #pragma unroll
        for (int i = 0; i < 4; i++)
            cp16((alo[i] ? AlS : AhS) + adst[i], agp[i], aval[i]);
        #pragma unroll
        for (int i = 0; i < 2; i++)
            cp16((blo[i] ? BlS : BhS) + bdst[i], bgp[i], true);
        asm volatile("cp.async.commit_group;\n");
    }

    for (int t = 0; t < T; t++) {
        int st = t & 1, nx = st ^ 1;
        if (t + 1 < T) {
            int k0 = (t + 1) * 32;
            #pragma unroll
            for (int i = 0; i < 4; i++)
                cp16((alo[i] ? AlS : AhS) + nx*STAGE_A + adst[i], agp[i] + k0, aval[i]);
            #pragma unroll
            for (int i = 0; i < 2; i++)
                cp16((blo[i] ? BlS : BhS) + nx*STAGE_B + bdst[i], bgp[i] + k0, true);
            asm volatile("cp.async.commit_group;\n");
            asm volatile("cp.async.wait_group 1;\n");
        } else {
            asm volatile("cp.async.wait_group 0;\n");
        }
        __syncthreads();

        const __nv_bfloat16* Ah = AhS + st*STAGE_A;
        const __nv_bfloat16* Al = AlS + st*STAGE_A;
        const __nv_bfloat16* Bh = BhS + st*STAGE_B;
        const __nv_bfloat16* Bl = BlS + st*STAGE_B;

        #pragma unroll
        for (int ks = 0; ks < 2; ks++) {
            int c0 = ks * 16 + 2*q;
            unsigned af[2][2][4];
            #pragma unroll
            for (int mt = 0; mt < 2; mt++) {
                int r = mbase + mt*16 + g;
                af[mt][0][0] = *reinterpret_cast<const unsigned*>(&Ah[r*SA + c0]);
                af[mt][0][1] = *reinterpret_cast<const unsigned*>(&Ah[(r+8)*SA + c0]);
                af[mt][0][2] = *reinterpret_cast<const unsigned*>(&Ah[r*SA + c0 + 8]);
                af[mt][0][3] = *reinterpret_cast<const unsigned*>(&Ah[(r+8)*SA + c0 + 8]);
                af[mt][1][0] = *reinterpret_cast<const unsigned*>(&Al[r*SA + c0]);
                af[mt][1][1] = *reinterpret_cast<const unsigned*>(&Al[(r+8)*SA + c0]);
                af[mt][1][2] = *reinterpret_cast<const unsigned*>(&Al[r*SA + c0 + 8]);
                af[mt][1][3] = *reinterpret_cast<const unsigned*>(&Al[(r+8)*SA + c0 + 8]);
            }
            unsigned bfr[4][2][2];
            #pragma unroll
            for (int nt = 0; nt < 4; nt++) {
                int n = nbase + nt*8 + g;
                bfr[nt][0][0] = *reinterpret_cast<const unsigned*>(&Bh[n*SA + c0]);
                bfr[nt][0][1] = *reinterpret_cast<const unsigned*>(&Bh[n*SA + c0 + 8]);
                bfr[nt][1][0] = *reinterpret_cast<const unsigned*>(&Bl[n*SA + c0]);
                bfr[nt][1][1] = *reinterpret_cast<const unsigned*>(&Bl[n*SA + c0 + 8]);
            }
            #pragma unroll
            for (int mt = 0; mt < 2; mt++)
                #pragma unroll
                for (int nt = 0; nt < 4; nt++) {
                    mma_bf16(acc[mt][nt], af[mt][0], bfr[nt][0]);
                    mma_bf16(acc[mt][nt], af[mt][0], bfr[nt][1]);
                    mma_bf16(acc[mt][nt], af[mt][1], bfr[nt][0]);
                }
        }
        __syncthreads();
    }

    #pragma unroll
    for (int mt = 0; mt < 2; mt++) {
        int r0 = m0 + mbase + mt*16 + g;
        int r1 = r0 + 8;
        bool ok0 = r0 < Meff, ok1 = r1 < Meff;
        if (CSCATTER) {
            int tok0 = 0, tok1 = 0; float w0 = 0.f, w1 = 0.f;
            if (ok0) { tok0 = lst[r0]; w0 = wl[r0]; }
            if (ok1) { tok1 = lst[r1]; w1 = wl[r1]; }
            #pragma unroll
            for (int nt = 0; nt < 4; nt++) {
                int col = n0 + nbase + nt*8 + 2*q;
                if (ok0) {
                    atomicAdd(&C[(long)tok0 * N + col],     w0 * acc[mt][nt][0]);
                    atomicAdd(&C[(long)tok0 * N + col + 1], w0 * acc[mt][nt][1]);
                }
                if (ok1) {
                    atomicAdd(&C[(long)tok1 * N + col],     w1 * acc[mt][nt][2]);
                    atomicAdd(&C[(long)tok1 * N + col + 1], w1 * acc[mt][nt][3]);
                }
            }
        } else {
            #pragma unroll
            for (int nt = 0; nt < 4; nt++) {
                int col = n0 + nbase + nt*8 + 2*q;
                if (ok0) *reinterpret_cast<float2*>(&C[(long)r0 * N + col]) =
                    make_float2(acc[mt][nt][0], acc[mt][nt][1]);
                if (ok1) *reinterpret_cast<float2*>(&C[(long)r1 * N + col]) =
                    make_float2(acc[mt][nt][2], acc[mt][nt][3]);
            }
        }
    }
}

// ---------------- fused a/b -> beta/decay (tiled, weight-reuse in smem) -----
__global__ void ab_kernel(const float* __restrict__ h,
                          const float* __restrict__ Wa, const float* __restrict__ Wb,
                          const float* __restrict__ dtb, const float* __restrict__ alog,
                          float* __restrict__ beta, float* __restrict__ decay) {
    __shared__ float Was[128][16], Wbs[128][16], hs[16][132];
    int tid = threadIdx.x;
    int tok = tid >> 4, hc = tid & 15;
    int t0 = blockIdx.x * 16;
    float accA = 0.f, accB = 0.f;
    for (int d0 = 0; d0 < DMODEL; d0 += 128) {
        #pragma unroll
        for (int i = 0; i < 8; i++) {
            int id = tid + 256*i;
            int d = id >> 4, c = id & 15;
            Was[d][c] = Wa[(long)(d0 + d) * HV + c];
            Wbs[d][c] = Wb[(long)(d0 + d) * HV + c];
        }
        #pragma unroll
        for (int i = 0; i < 8; i++) {
            int id = tid + 256*i;
            int tk = id >> 7, d = id & 127;
            hs[tk][d] = h[(long)(t0 + tk) * DMODEL + d0 + d];
        }
        __syncthreads();
        #pragma unroll
        for (int d = 0; d < 128; d++) {
            float hv = hs[tok][d];
            accA += hv * Was[d][hc];
            accB += hv * Wbs[d][hc];
        }
        __syncthreads();
    }
    int idx = (t0 + tok) * HV + hc;
    beta[idx] = sigmoidf(accB);
    float xv = accA + dtb[hc];
    float sp = (xv > 20.f) ? xv : log1pf(expf(xv));
    decay[idx] = expf(-expf(alog[hc]) * sp);
}

// ---------------- depthwise causal conv + silu (reads fused qkvz) ----------
__global__ void conv_silu_kernel(const float* __restrict__ qkvz,
                                 const float* __restrict__ conv_state,
                                 const float* __restrict__ w,
                                 float* __restrict__ out) {
    long idx = (long)blockIdx.x * blockDim.x + threadIdx.x;
    if (idx >= (long)SEQ * CONVD) return;
    int s = (int)(idx / CONVD);
    int c = (int)(idx % CONVD);
    float acc = 0.f;
    #pragma unroll
    for (int j = 0; j < KW; j++) {
        int p = s + j;
        float xv = (p < KW-1) ? conv_state[(long)p * CONVD + c]
                              : qkvz[(long)(p - (KW-1)) * QZD + c];
        acc += xv * w[c * KW + j];
    }
    out[idx] = siluf(acc);
}

__global__ void conv_state_out_kernel(const float* __restrict__ qkvz, float* __restrict__ out) {
    int i = blockIdx.x * blockDim.x + threadIdx.x;
    if (i >= (KW-1) * CONVD) return;
    int row = i / CONVD, col = i % CONVD;
    out[i] = qkvz[(long)(SEQ - (KW-1) + row) * QZD + col];
}

// ---------------- l2norm q,k + repeat ----------------
__global__ void l2norm_kernel(const float* __restrict__ qkv,
                              float* __restrict__ qn, float* __restrict__ kn) {
    int gw = blockIdx.x * 8 + (threadIdx.x >> 5);
    int lane = threadIdx.x & 31;
    int s = gw >> 4, rr = gw & 15;
    bool isq = rr < 8;
    int hk = isq ? rr : rr - 8;
    long base = (long)s * CONVD + (isq ? 0 : KEYD) + hk * 64;
    float v0 = qkv[base + lane];
    float v1 = qkv[base + 32 + lane];
    float ss = warp_reduce(v0*v0 + v1*v1);
    float r = rsqrtf(ss + 1e-6f);
    float sc = isq ? 0.125f : 1.f;
    float o0 = v0 * r * sc, o1 = v1 * r * sc;
    float* dst = isq ? qn : kn;
    long b0 = (long)s * VALD + (2*hk) * 64;
    long b1 = (long)s * VALD + (2*hk + 1) * 64;
    dst[b0 + lane] = o0;  dst[b0 + 32 + lane] = o1;
    dst[b1 + lane] = o0;  dst[b1 + 32 + lane] = o1;
}

// ---------------- sequential delta-rule scan (double-buffered, 1 bar/step) --
__global__ void scan_kernel(const float* __restrict__ qn, const float* __restrict__ kn,
                            const float* __restrict__ qkv,
                            const float* __restrict__ decay, const float* __restrict__ beta,
                            const float* __restrict__ state_in,
                            float* __restrict__ o, float* __restrict__ state_out) {
    int h  = blockIdx.x >> 2;
    int cg = blockIdx.x & 3;
    int tid  = threadIdx.x;
    int vloc = tid >> 4, g = tid & 15;
    int v = cg * 16 + vloc;
    __shared__ float ks[2][64], qs[2][64], vs[2][64], sc[2][2];
    float Sreg[4];
    #pragma unroll
    for (int i = 0; i < 4; i++) {
        int r = g + 16*i;
        Sreg[i] = state_in[(long)h * DK * DV + (long)r * DV + v];
    }
    // preload s=0
    if (tid < 64)        ks[0][tid]       = kn[h*64 + tid];
    else if (tid < 128)  qs[0][tid-64]    = qn[h*64 + (tid-64)];
    else if (tid < 192)  vs[0][tid-128]   = qkv[2*KEYD + h*64 + (tid-128)];
    else if (tid == 192) sc[0][0] = decay[h];
    else if (tid == 193) sc[0][1] = beta[h];
    __syncthreads();
    for (int s = 0; s < SEQ; s++) {
        int cur = s & 1, nx = cur ^ 1;
        if (s + 1 < SEQ) {
            long sn = s + 1;
            if (tid < 64)        ks[nx][tid]     = kn[sn*VALD + h*64 + tid];
            else if (tid < 128)  qs[nx][tid-64]  = qn[sn*VALD + h*64 + (tid-64)];
            else if (tid < 192)  vs[nx][tid-128] = qkv[sn*CONVD + 2*KEYD + h*64 + (tid-128)];
            else if (tid == 192) sc[nx][0] = decay[sn*HV + h];
            else if (tid == 193) sc[nx][1] = beta[sn*HV + h];
        }
        float dec = sc[cur][0], bet = sc[cur][1], vv = vs[cur][v];
        float kr[4], qr[4];
        #pragma unroll
        for (int i = 0; i < 4; i++) { kr[i] = ks[cur][g + 16*i]; qr[i] = qs[cur][g + 16*i]; }
        float pm = 0.f;
        #pragma unroll
        for (int i = 0; i < 4; i++) { Sreg[i] *= dec; pm += kr[i] * Sreg[i]; }
        #pragma unroll
        for (int off = 8; off > 0; off >>= 1) pm += __shfl_xor_sync(0xffffffffu, pm, off);
        float delta = (vv - pm) * bet;
        float po = 0.f;
        #pragma unroll
        for (int i = 0; i < 4; i++) { Sreg[i] += kr[i] * delta; po += qr[i] * Sreg[i]; }
        #pragma unroll
        for (int off = 8; off > 0; off >>= 1) po += __shfl_xor_sync(0xffffffffu, po, off);
        if (g == 0) o[(long)s * VALD + h*64 + v] = po;
        __syncthreads();
    }
    #pragma unroll
    for (int i = 0; i < 4; i++) {
        int r = g + 16*i;
        state_out[(long)h * DK * DV + (long)r * DV + v] = Sreg[i];
    }
}

// ---------------- gated rms-norm, writes bf16 hi/lo ----------------
__global__ void gated_norm_kernel(const float* __restrict__ o, const float* __restrict__ zbase,
                                  const float* __restrict__ nw,
                                  __nv_bfloat16* __restrict__ oh, __nv_bfloat16* __restrict__ ol) {
    int gw = blockIdx.x * 8 + (threadIdx.x >> 5);
    int lane = threadIdx.x & 31;
    int s = gw >> 4, h = gw & 15;
    long base = (long)s * VALD + h * 64;
    long zb   = (long)s * QZD + h * 64;     // zbase already offset by CONVD
    float o0 = o[base + lane], o1 = o[base + 32 + lane];
    float ss = warp_reduce(o0*o0 + o1*o1);
    float r = rsqrtf(ss / 64.f + 1e-6f);
    float w0 = 1.f + nw[h*64 + lane], w1 = 1.f + nw[h*64 + 32 + lane];
    float z0 = zbase[zb + lane], z1 = zbase[zb + 32 + lane];
    float r0 = o0 * r * w0 * siluf(z0);
    float r1 = o1 * r * w1 * siluf(z1);
    __nv_bfloat16 hh, hl;
    split_bf16(r0, hh, hl); oh[base + lane] = hh; ol[base + lane] = hl;
    split_bf16(r1, hh, hl); oh[base + 32 + lane] = hh; ol[base + 32 + lane] = hl;
}

// ---------------- router ----------------
__global__ void router_kernel(const float* __restrict__ t, const float* __restrict__ rw,
                              int* __restrict__ topi, float* __restrict__ topw) {
    int tok = blockIdx.x;
    int wrp = threadIdx.x >> 5, lane = threadIdx.x & 31;
    __shared__ float lg[NE];
    const float* row = t + (long)tok * DMODEL;
    const float* wr = rw + (long)wrp * DMODEL;
    float s = 0.f;
    for (int d = lane; d < DMODEL; d += 32) s += row[d] * wr[d];
    s = warp_reduce(s);
    if (lane == 0) lg[wrp] = s;
    __syncthreads();
    if (threadIdx.x == 0) {
        float mx = -1e30f;
        #pragma unroll
        for (int e = 0; e < NE; e++) mx = fmaxf(mx, lg[e]);
        float ex[NE];
        #pragma unroll
        for (int e = 0; e < NE; e++) ex[e] = expf(lg[e] - mx);
        int b0 = 0; float p0 = -1.f;
        #pragma unroll
        for (int e = 0; e < NE; e++) if (ex[e] > p0) { p0 = ex[e]; b0 = e; }
        int b1 = -1; float p1 = -1.f;
        #pragma unroll
        for (int e = 0; e < NE; e++) if (e != b0 && ex[e] > p1) { p1 = ex[e]; b1 = e; }
        float tot = p0 + p1;
        topi[tok*2] = b0;  topi[tok*2 + 1] = b1;
        topw[tok*2] = p0 / tot;  topw[tok*2 + 1] = p1 / tot;
    }
}

__global__ void zero_kernel(float* __restrict__ routed, int* __restrict__ cnt) {
    long i = (long)blockIdx.x * blockDim.x + threadIdx.x;
    if (i < (long)SEQ * DMODEL) routed[i] = 0.f;
    if (i < NE) cnt[i] = 0;
}

__global__ void build_kernel(const int* __restrict__ topi, const float* __restrict__ topw,
                             int* __restrict__ cnt, int* __restrict__ list,
                             float* __restrict__ lw) {
    int tok = blockIdx.x * blockDim.x + threadIdx.x;
    if (tok >= SEQ) return;
    #pragma unroll
    for (int j = 0; j < TOPK; j++) {
        int e = topi[tok*2 + j];
        int pos = atomicAdd(&cnt[e], 1);
        list[e * SEQ + pos] = tok;
        lw[e * SEQ + pos]   = topw[tok*2 + j];
    }
}

__global__ void moe_act_kernel(const float* __restrict__ gu, const int* __restrict__ cnt,
                               __nv_bfloat16* __restrict__ acth, __nv_bfloat16* __restrict__ actl) {
    int e = blockIdx.z;
    int idx = blockIdx.x * blockDim.x + threadIdx.x;
    int row = idx >> 9, i = idx & 511;
    if (row >= cnt[e]) return;
    long b = (long)e * SEQ * 1024 + (long)row * 1024;
    float gt = gu[b + i], up = gu[b + 512 + i];
    float v = siluf(gt) * up;
    long o = (long)e * SEQ * IMOE + (long)row * IMOE + i;
    __nv_bfloat16 h, l; split_bf16(v, h, l);
    acth[o] = h; actl[o] = l;
}

__global__ void act2_kernel(const float* __restrict__ sgu,
                            __nv_bfloat16* __restrict__ oh, __nv_bfloat16* __restrict__ ol) {
    long i = (long)blockIdx.x * blockDim.x + threadIdx.x;
    if (i >= (long)SEQ * VALD) return;
    int row = (int)(i >> 10), n = (int)(i & 1023);
    float gv = sgu[(long)row * 2048 + n];
    float uv = sgu[(long)row * 2048 + 1024 + n];
    float v = siluf(gv) * uv;
    __nv_bfloat16 h, l; split_bf16(v, h, l);
    oh[i] = h; ol[i] = l;
}

__global__ void gate_kernel(const float* __restrict__ t, const float* __restrict__ wg,
                            float* __restrict__ gate) {
    int tok = blockIdx.x * 8 + (threadIdx.x >> 5);
    int lane = threadIdx.x & 31;
    const float* row = t + (long)tok * DMODEL;
    float s = 0.f;
    for (int d = lane; d < DMODEL; d += 32) s += row[d] * wg[d];
    s = warp_reduce(s);
    if (lane == 0) gate[tok] = sigmoidf(s);
}

__global__ void final_kernel(const float* __restrict__ x2, const float* __restrict__ routed,
                             const float* __restrict__ sh, const float* __restrict__ gate,
                             float* __restrict__ out) {
    long i = (long)blockIdx.x * blockDim.x + threadIdx.x;
    if (i >= (long)SEQ * DMODEL) return;
    int row = (int)(i >> 10);
    out[i] = x2[i] + routed[i] + sh[i] * gate[row];
}

// ---------------- host launch ----------------
extern "C" void kernel_launch(void* const* d_in, const int* in_sizes, int n_in,
                              void* d_out, int out_size) {
    const float* x        = (const float*)d_in[0];
    const float* state    = (const float*)d_in[1];
    const float* cstate   = (const float*)d_in[2];
    const float* Wqkv     = (const float*)d_in[3];
    const float* Wz       = (const float*)d_in[4];
    const float* Wa       = (const float*)d_in[5];
    const float* Wb       = (const float*)d_in[6];
    const float* convW    = (const float*)d_in[7];
    const float* dt_bias  = (const float*)d_in[8];
    const float* A_log    = (const float*)d_in[9];
    const float* norm_w   = (const float*)d_in[10];
    const float* Wout     = (const float*)d_in[11];
    const float* routerW  = (const float*)d_in[12];
    const float* Wegu     = (const float*)d_in[13];
    const float* Wed      = (const float*)d_in[14];
    const float* Wsg      = (const float*)d_in[15];
    const float* Wsu      = (const float*)d_in[16];
    const float* Wsd      = (const float*)d_in[17];
    const float* Wseg     = (const float*)d_in[18];
    const float* attn_nw  = (const float*)d_in[19];
    const float* ffn_nw   = (const float*)d_in[20];
    float* out = (float*)d_out;

    float *ph, *pqkvz, *pqkv, *pqn, *pkn, *pbeta, *pdecay, *po, *pattn, *px2, *pt;
    float *ptopw, *plw, *pgu, *prouted, *psgu, *psh, *pgate;
    int *ptopi, *pcnt, *plist;
    __nv_bfloat16 *phh, *phl, *poh, *pol, *pth, *ptl, *pacth, *pactl, *psgh, *psgl;
    __nv_bfloat16 *wqzh, *wqzl, *wouth, *woutl, *wguh, *wgul, *wsdh, *wsdl, *eguh, *egul, *edh, *edl;

    cudaGetSymbolAddress((void**)&ph,     g_h);
    cudaGetSymbolAddress((void**)&phh,    g_hh);
    cudaGetSymbolAddress((void**)&phl,    g_hl);
    cudaGetSymbolAddress((void**)&pqkvz,  g_qkvz);
    cudaGetSymbolAddress((void**)&pqkv,   g_qkv);
    cudaGetSymbolAddress((void**)&pqn,    g_qn);
    cudaGetSymbolAddress((void**)&pkn,    g_kn);
    cudaGetSymbolAddress((void**)&pbeta,  g_beta);
    cudaGetSymbolAddress((void**)&pdecay, g_decay);
    cudaGetSymbolAddress((void**)&po,     g_o);
    cudaGetSymbolAddress((void**)&poh,    g_oh);
    cudaGetSymbolAddress((void**)&pol,    g_ol);
    cudaGetSymbolAddress((void**)&pattn,  g_attn);
    cudaGetSymbolAddress((void**)&px2,    g_x2);
    cudaGetSymbolAddress((void**)&pt,     g_t);
    cudaGetSymbolAddress((void**)&pth,    g_th);
    cudaGetSymbolAddress((void**)&ptl,    g_tl);
    cudaGetSymbolAddress((void**)&ptopi,  g_topi);
    cudaGetSymbolAddress((void**)&ptopw,  g_topw);
    cudaGetSymbolAddress((void**)&pcnt,   g_cnt);
    cudaGetSymbolAddress((void**)&plist,  g_list);
    cudaGetSymbolAddress((void**)&plw,    g_lw);
    cudaGetSymbolAddress((void**)&pgu,    g_gu);
    cudaGetSymbolAddress((void**)&pacth,  g_acth);
    cudaGetSymbolAddress((void**)&pactl,  g_actl);
    cudaGetSymbolAddress((void**)&prouted,g_routed);
    cudaGetSymbolAddress((void**)&psgu,   g_sgu);
    cudaGetSymbolAddress((void**)&psgh,   g_sgh);
    cudaGetSymbolAddress((void**)&psgl,   g_sgl);
    cudaGetSymbolAddress((void**)&psh,    g_sh);
    cudaGetSymbolAddress((void**)&pgate,  g_gate);
    cudaGetSymbolAddress((void**)&wqzh,   g_wqzT_h);
    cudaGetSymbolAddress((void**)&wqzl,   g_wqzT_l);
    cudaGetSymbolAddress((void**)&wouth,  g_woutT_h);
    cudaGetSymbolAddress((void**)&woutl,  g_woutT_l);
    cudaGetSymbolAddress((void**)&wguh,   g_wguT_h);
    cudaGetSymbolAddress((void**)&wgul,   g_wguT_l);
    cudaGetSymbolAddress((void**)&wsdh,   g_wsdT_h);
    cudaGetSymbolAddress((void**)&wsdl,   g_wsdT_l);
    cudaGetSymbolAddress((void**)&eguh,   g_egu_h);
    cudaGetSymbolAddress((void**)&egul,   g_egu_l);
    cudaGetSymbolAddress((void**)&edh,    g_ed_h);
    cudaGetSymbolAddress((void**)&edl,    g_ed_l);

    cudaFuncSetAttribute(gemm_bf16_kernel<false,false>,
                         cudaFuncAttributeMaxDynamicSharedMemorySize, GEMM_SMEM);
    cudaFuncSetAttribute(gemm_bf16_kernel<true,false>,
                         cudaFuncAttributeMaxDynamicSharedMemorySize, GEMM_SMEM);
    cudaFuncSetAttribute(gemm_bf16_kernel<false,true>,
                         cudaFuncAttributeMaxDynamicSharedMemorySize, GEMM_SMEM);

    dim3 blk(256);

    // ---- weight prep (transpose+split / split) ----
    tsplit_kernel<<<dim3(CONVD/32, DMODEL/32), 256>>>(Wqkv, wqzh, wqzl, DMODEL, CONVD);
    tsplit_kernel<<<dim3(VALD/32, DMODEL/32), 256>>>(Wz, wqzh + (long)CONVD*DMODEL,
                                                     wqzl + (long)CONVD*DMODEL, DMODEL, VALD);
    tsplit_kernel<<<dim3(DMODEL/32, VALD/32), 256>>>(Wout, wouth, woutl, VALD, DMODEL);
    tsplit_kernel<<<dim3(VALD/32, DMODEL/32), 256>>>(Wsg, wguh, wgul, DMODEL, VALD);
    tsplit_kernel<<<dim3(VALD/32, DMODEL/32), 256>>>(Wsu, wguh + (long)VALD*DMODEL,
                                                     wgul + (long)VALD*DMODEL, DMODEL, VALD);
    tsplit_kernel<<<dim3(DMODEL/32, VALD/32), 256>>>(Wsd, wsdh, wsdl, VALD, DMODEL);
    split_kernel<<<(int)(((long)NE*1024*DMODEL + 255)/256), 256>>>(Wegu, eguh, egul, (long)NE*1024*DMODEL);
    split_kernel<<<(int)(((long)NE*DMODEL*IMOE + 255)/256), 256>>>(Wed, edh, edl, (long)NE*DMODEL*IMOE);

    // 1. attention rms norm (+ bf16 split)
    rmsnorm_kernel<<<SEQ, 256>>>(x, attn_nw, ph, phh, phl);

    // 2. fused qkv|z projection (N=3072); fused a/b -> beta,decay
    gemm_bf16_kernel<false,false><<<dim3(QZD/64, SEQ/128, 1), blk, GEMM_SMEM>>>(
        phh, phl, wqzh, wqzl, pqkvz, SEQ, QZD, DMODEL, 0,0,0, nullptr,nullptr,nullptr,0);
    ab_kernel<<<SEQ/16, 256>>>(ph, Wa, Wb, dt_bias, A_log, pbeta, pdecay);

    conv_state_out_kernel<<<((KW-1)*CONVD + 255)/256, 256>>>(pqkvz, out + OUT_CONV_OFF);
    conv_silu_kernel<<<(SEQ*CONVD + 255)/256, 256>>>(pqkvz, cstate, convW, pqkv);
    l2norm_kernel<<<SEQ*16/8, 256>>>(pqkv, pqn, pkn);

    // 3. scan
    scan_kernel<<<64, 256>>>(pqn, pkn, pqkv, pdecay, pbeta, state, po, out + OUT_STATE_OFF);

    // 4. gated norm -> bf16
    gated_norm_kernel<<<SEQ*16/8, 256>>>(po, pqkvz + CONVD, norm_w, poh, pol);

    // 5. out projection; then x2 = x + attn, t = rmsnorm(x2) (+ split)
    gemm_bf16_kernel<false,false><<<dim3(DMODEL/64, SEQ/128, 1), blk, GEMM_SMEM>>>(
        poh, pol, wouth, woutl, pattn, SEQ, DMODEL, VALD, 0,0,0, nullptr,nullptr,nullptr,0);
    rmsnorm_add_kernel<<<SEQ, 256>>>(x, pattn, ffn_nw, px2, pt, pth, ptl);

    // 6. router + lists
    router_kernel<<<SEQ, 256>>>(pt, routerW, ptopi, ptopw);
    zero_kernel<<<(SEQ*DMODEL + 255)/256, 256>>>(prouted, pcnt);
    build_kernel<<<(SEQ + 255)/256, 256>>>(ptopi, ptopw, pcnt, plist, plw);

    // 7. routed experts
    gemm_bf16_kernel<true,false><<<dim3(1024/64, SEQ/128, NE), blk, GEMM_SMEM>>>(
        pth, ptl, eguh, egul, pgu, SEQ, 2*IMOE, DMODEL,
        0, (long)2*IMOE*DMODEL, (long)SEQ*1024, plist, pcnt, plw, SEQ);
    moe_act_kernel<<<dim3(SEQ*IMOE/256, 1, NE), 256>>>(pgu, pcnt, pacth, pactl);
    gemm_bf16_kernel<false,true><<<dim3(DMODEL/64, SEQ/128, NE), blk, GEMM_SMEM>>>(
        pacth, pactl, edh, edl, prouted, SEQ, DMODEL, IMOE,
        (long)SEQ*IMOE, (long)DMODEL*IMOE, 0, plist, pcnt, plw, SEQ);

    // 8. shared expert (fused gate|up N=2048, then down)
    gemm_bf16_kernel<false,false><<<dim3(2048/64, SEQ/128, 1), blk, GEMM_SMEM>>>(
        pth, ptl, wguh, wgul, psgu, SEQ, 2048, DMODEL, 0,0,0, nullptr,nullptr,nullptr,0);
    act2_kernel<<<(SEQ*VALD + 255)/256, 256>>>(psgu, psgh, psgl);
    gemm_bf16_kernel<false,false><<<dim3(DMODEL/64, SEQ/128, 1), blk, GEMM_SMEM>>>(
        psgh, psgl, wsdh, wsdl, psh, SEQ, DMODEL, VALD, 0,0,0, nullptr,nullptr,nullptr,0);
    gate_kernel<<<SEQ/8, 256>>>(pt, Wseg, pgate);

    // 9. final combine
    final_kernel<<<(SEQ*DMODEL + 255)/256, 256>>>(px2, prouted, psh, pgate, out + OUT_X_OFF);
}